// round 1
// baseline (speedup 1.0000x reference)
#include <cuda_runtime.h>
#include <cuda_bf16.h>
#include <math.h>

#define NN 50000
#define DD 128
#define EE 800000
#define TM 64
#define XPITCH 132

// -------- device scratch (no runtime allocation allowed) --------
__device__ float g_b[2 * NN];               // boundary scores
__device__ float g_t[2 * (size_t)NN * DD];  // per-type transformed features (51.2MB)
__device__ float g_upd[2 * (size_t)NN * DD];// x + aggregated messages (51.2MB)
__device__ float g_c[2 * EE];               // per-edge coefficient ea*w

// ---------------------------------------------------------------
// 0) init: upd = x  (residual folded in)
// ---------------------------------------------------------------
__global__ void init_upd_kernel(const float* __restrict__ x) {
    size_t i = (size_t)blockIdx.x * blockDim.x + threadIdx.x;
    size_t total = (size_t)2 * NN * DD / 4;
    if (i < total) ((float4*)g_upd)[i] = ((const float4*)x)[i];
}

// ---------------------------------------------------------------
// 1) boundary MLP: b[t][n] = sigmoid(MLP(x[t][n]))   128->64->32->1
//    one thread per node; weights staged in shared.
// ---------------------------------------------------------------
__global__ __launch_bounds__(128) void boundary_kernel(
    const float* __restrict__ x,
    const float* __restrict__ bdW1, const float* __restrict__ bdb1,
    const float* __restrict__ bdW2, const float* __restrict__ bdb2,
    const float* __restrict__ bdW3, const float* __restrict__ bdb3)
{
    __shared__ float W1s[128 * 64];   // 32KB
    __shared__ float W2s[64 * 32];    // 8KB
    __shared__ float W3s[32];
    __shared__ float b1s[64], b2s[32];
    __shared__ float b3s;

    int type = blockIdx.y;
    int tid = threadIdx.x;
    const float* W1 = bdW1 + (size_t)type * 128 * 64;
    const float* W2 = bdW2 + (size_t)type * 64 * 32;
    for (int i = tid; i < 128 * 64; i += 128) W1s[i] = W1[i];
    for (int i = tid; i < 64 * 32; i += 128) W2s[i] = W2[i];
    if (tid < 32) W3s[tid] = bdW3[type * 32 + tid];
    if (tid < 64) b1s[tid] = bdb1[type * 64 + tid];
    if (tid < 32) b2s[tid] = bdb2[type * 32 + tid];
    if (tid == 0) b3s = bdb3[type];
    __syncthreads();

    int node = blockIdx.x * 128 + tid;
    if (node >= NN) return;

    const float4* xr = (const float4*)(x + ((size_t)type * NN + node) * DD);

    float h1[64];
#pragma unroll
    for (int j = 0; j < 64; j++) h1[j] = b1s[j];

    for (int d4 = 0; d4 < 32; d4++) {
        float4 xv = xr[d4];
        float vs[4] = {xv.x, xv.y, xv.z, xv.w};
#pragma unroll
        for (int dd = 0; dd < 4; dd++) {
            float v = vs[dd];
            const float4* wr = (const float4*)&W1s[(d4 * 4 + dd) * 64];
#pragma unroll
            for (int q = 0; q < 16; q++) {
                float4 w = wr[q];
                h1[q * 4 + 0] += v * w.x;
                h1[q * 4 + 1] += v * w.y;
                h1[q * 4 + 2] += v * w.z;
                h1[q * 4 + 3] += v * w.w;
            }
        }
    }
#pragma unroll
    for (int j = 0; j < 64; j++) h1[j] = fmaxf(h1[j], 0.f);

    float h2[32];
#pragma unroll
    for (int j = 0; j < 32; j++) h2[j] = b2s[j];
#pragma unroll
    for (int k = 0; k < 64; k++) {
        float v = h1[k];
        const float4* wr = (const float4*)&W2s[k * 32];
#pragma unroll
        for (int q = 0; q < 8; q++) {
            float4 w = wr[q];
            h2[q * 4 + 0] += v * w.x;
            h2[q * 4 + 1] += v * w.y;
            h2[q * 4 + 2] += v * w.z;
            h2[q * 4 + 3] += v * w.w;
        }
    }
    float z = b3s;
#pragma unroll
    for (int k = 0; k < 32; k++) z += fmaxf(h2[k], 0.f) * W3s[k];

    g_b[type * NN + node] = 1.f / (1.f + expf(-z));
}

// ---------------------------------------------------------------
// shared GEMM microkernel: C(64x128) += Xs(64x128) * Ws(128x128)
// thread layout 16x16, 4 rows x 8 cols per thread
// ---------------------------------------------------------------
__device__ __forceinline__ void gemm_tile(const float* Xs, const float* Ws,
                                          float acc[4][8], int tx, int ty)
{
#pragma unroll 4
    for (int k = 0; k < 128; k++) {
        float a0 = Xs[(ty * 4 + 0) * XPITCH + k];
        float a1 = Xs[(ty * 4 + 1) * XPITCH + k];
        float a2 = Xs[(ty * 4 + 2) * XPITCH + k];
        float a3 = Xs[(ty * 4 + 3) * XPITCH + k];
        const float4* wp = (const float4*)&Ws[k * 128 + tx * 8];
        float4 w0 = wp[0], w1 = wp[1];
        float wv[8] = {w0.x, w0.y, w0.z, w0.w, w1.x, w1.y, w1.z, w1.w};
#pragma unroll
        for (int j = 0; j < 8; j++) {
            acc[0][j] += a0 * wv[j];
            acc[1][j] += a1 * wv[j];
            acc[2][j] += a2 * wv[j];
            acc[3][j] += a3 * wv[j];
        }
    }
}

// ---------------------------------------------------------------
// 2) edge-type transform: t = relu(x @ W1 + b1) @ W2 + b2, fused 2-layer
// ---------------------------------------------------------------
__global__ __launch_bounds__(256, 2) void et_kernel(
    const float* __restrict__ x,
    const float* __restrict__ W1g, const float* __restrict__ b1g,
    const float* __restrict__ W2g, const float* __restrict__ b2g)
{
    extern __shared__ float sm[];
    float* Xs = sm;                  // TM * XPITCH
    float* Ws = sm + TM * XPITCH;    // 128 * 128

    int type = blockIdx.y;
    int m0 = blockIdx.x * TM;
    int tid = threadIdx.x;
    int tx = tid & 15, ty = tid >> 4;
    const float* xb = x + (size_t)type * NN * DD;

    for (int i = tid; i < TM * 32; i += 256) {
        int r = i >> 5, c4 = i & 31;
        int row = m0 + r;
        float4 v = (row < NN) ? ((const float4*)(xb + (size_t)row * DD))[c4]
                              : make_float4(0.f, 0.f, 0.f, 0.f);
        float* dst = &Xs[r * XPITCH + c4 * 4];
        dst[0] = v.x; dst[1] = v.y; dst[2] = v.z; dst[3] = v.w;
    }
    {
        const float4* W1 = (const float4*)(W1g + (size_t)type * 128 * 128);
        for (int i = tid; i < 128 * 32; i += 256) ((float4*)Ws)[i] = W1[i];
    }
    __syncthreads();

    float acc[4][8];
    {
        const float* b1 = b1g + type * 128 + tx * 8;
#pragma unroll
        for (int j = 0; j < 8; j++) {
            float bv = b1[j];
            acc[0][j] = bv; acc[1][j] = bv; acc[2][j] = bv; acc[3][j] = bv;
        }
    }
    gemm_tile(Xs, Ws, acc, tx, ty);
    __syncthreads();

    // relu -> H (reuse Xs), load W2
#pragma unroll
    for (int i = 0; i < 4; i++)
#pragma unroll
        for (int j = 0; j < 8; j++)
            Xs[(ty * 4 + i) * XPITCH + tx * 8 + j] = fmaxf(acc[i][j], 0.f);
    {
        const float4* W2 = (const float4*)(W2g + (size_t)type * 128 * 128);
        for (int i = tid; i < 128 * 32; i += 256) ((float4*)Ws)[i] = W2[i];
    }
    __syncthreads();

    {
        const float* b2 = b2g + type * 128 + tx * 8;
#pragma unroll
        for (int j = 0; j < 8; j++) {
            float bv = b2[j];
            acc[0][j] = bv; acc[1][j] = bv; acc[2][j] = bv; acc[3][j] = bv;
        }
    }
    gemm_tile(Xs, Ws, acc, tx, ty);

    float* tb = g_t + (size_t)type * NN * DD;
#pragma unroll
    for (int i = 0; i < 4; i++) {
        int row = m0 + ty * 4 + i;
        if (row < NN) {
            float4* op = (float4*)(tb + (size_t)row * DD + tx * 8);
            op[0] = make_float4(acc[i][0], acc[i][1], acc[i][2], acc[i][3]);
            op[1] = make_float4(acc[i][4], acc[i][5], acc[i][6], acc[i][7]);
        }
    }
}

// ---------------------------------------------------------------
// 3) per-edge coefficient: c = ea * w,  w = (boundary-MLP on (sb,db))
// ---------------------------------------------------------------
__global__ __launch_bounds__(256) void coef_kernel(
    const int* __restrict__ ei, const float* __restrict__ ea,
    const float* __restrict__ bwW1, const float* __restrict__ bwb1,
    const float* __restrict__ bwW2, const float* __restrict__ bwb2,
    const float* __restrict__ bwW3, const float* __restrict__ bwb3)
{
    __shared__ float W1s[64], B1s[32], W2s[512], B2s[16], W3s[16];
    __shared__ float B3s;
    int type = blockIdx.y;
    int tid = threadIdx.x;
    if (tid < 64) W1s[tid] = bwW1[type * 64 + tid];
    if (tid < 32) B1s[tid] = bwb1[type * 32 + tid];
    for (int i = tid; i < 512; i += 256) W2s[i] = bwW2[type * 512 + i];
    if (tid < 16) B2s[tid] = bwb2[type * 16 + tid];
    if (tid < 16) W3s[tid] = bwW3[type * 16 + tid];
    if (tid == 0) B3s = bwb3[type];
    __syncthreads();

    int j = blockIdx.x * 256 + tid;
    if (j >= EE) return;
    const int* eib = ei + (size_t)type * 2 * EE;
    int s = eib[j];
    int d = eib[EE + j];
    float sb = g_b[type * NN + s];
    float db = g_b[(1 - type) * NN + d];

    float h1[32];
#pragma unroll
    for (int q = 0; q < 32; q++)
        h1[q] = fmaxf(sb * W1s[q] + db * W1s[32 + q] + B1s[q], 0.f);

    float h2[16];
#pragma unroll
    for (int p = 0; p < 16; p++) h2[p] = B2s[p];
#pragma unroll
    for (int q = 0; q < 32; q++) {
        float v = h1[q];
#pragma unroll
        for (int p = 0; p < 16; p++) h2[p] += v * W2s[q * 16 + p];
    }
    float z = B3s;
#pragma unroll
    for (int p = 0; p < 16; p++) z += fmaxf(h2[p], 0.f) * W3s[p];

    float w = 1.f / (1.f + expf(-z));
    if (sb > 0.3f || db > 0.3f) w *= 2.f;
    g_c[(size_t)type * EE + j] = ea[(size_t)type * EE + j] * w;
}

// ---------------------------------------------------------------
// 4) scatter: upd[1-e][dst] += t[e][src] * c    (warp per edge)
// ---------------------------------------------------------------
__global__ __launch_bounds__(256) void scatter_kernel(const int* __restrict__ ei)
{
    int type = blockIdx.y;
    int lane = threadIdx.x & 31;
    int warp = threadIdx.x >> 5;
    long j = (long)blockIdx.x * 8 + warp;
    if (j >= EE) return;
    const int* eib = ei + (size_t)type * 2 * EE;
    int s = eib[j];
    int d = eib[EE + j];
    float c = g_c[(size_t)type * EE + j];

    float4 v = ((const float4*)(g_t + ((size_t)type * NN + s) * DD))[lane];
    float* outp = g_upd + ((size_t)(1 - type) * NN + d) * DD + lane * 4;
    atomicAdd(outp + 0, v.x * c);
    atomicAdd(outp + 1, v.y * c);
    atomicAdd(outp + 2, v.z * c);
    atomicAdd(outp + 3, v.w * c);
}

// ---------------------------------------------------------------
// 5) node update: out = relu(LN(upd @ nuW + nub) * g + b)
// ---------------------------------------------------------------
__global__ __launch_bounds__(256, 2) void nu_kernel(
    const float* __restrict__ nuW, const float* __restrict__ nub,
    const float* __restrict__ lng, const float* __restrict__ lnb,
    float* __restrict__ out)
{
    extern __shared__ float sm[];
    float* Us = sm;                         // TM * XPITCH
    float* Ws = sm + TM * XPITCH;           // 128*128
    float* muS = Ws + 128 * 128;            // 64
    float* rsS = muS + 64;                  // 64

    int type = blockIdx.y;
    int m0 = blockIdx.x * TM;
    int tid = threadIdx.x;
    int tx = tid & 15, ty = tid >> 4;
    const float* ub = g_upd + (size_t)type * NN * DD;

    for (int i = tid; i < TM * 32; i += 256) {
        int r = i >> 5, c4 = i & 31;
        int row = m0 + r;
        float4 v = (row < NN) ? ((const float4*)(ub + (size_t)row * DD))[c4]
                              : make_float4(0.f, 0.f, 0.f, 0.f);
        float* dst = &Us[r * XPITCH + c4 * 4];
        dst[0] = v.x; dst[1] = v.y; dst[2] = v.z; dst[3] = v.w;
    }
    {
        const float4* W = (const float4*)(nuW + (size_t)type * 128 * 128);
        for (int i = tid; i < 128 * 32; i += 256) ((float4*)Ws)[i] = W[i];
    }
    __syncthreads();

    float acc[4][8];
    {
        const float* bb = nub + type * 128 + tx * 8;
#pragma unroll
        for (int j = 0; j < 8; j++) {
            float bv = bb[j];
            acc[0][j] = bv; acc[1][j] = bv; acc[2][j] = bv; acc[3][j] = bv;
        }
    }
    gemm_tile(Us, Ws, acc, tx, ty);
    __syncthreads();

    // write z back into Us for LN
#pragma unroll
    for (int i = 0; i < 4; i++)
#pragma unroll
        for (int j = 0; j < 8; j++)
            Us[(ty * 4 + i) * XPITCH + tx * 8 + j] = acc[i][j];
    __syncthreads();

    if (tid < 64) {
        const float* zr = &Us[tid * XPITCH];
        float s = 0.f;
        for (int c = 0; c < 128; c++) s += zr[c];
        float mu = s * (1.f / 128.f);
        float v = 0.f;
        for (int c = 0; c < 128; c++) { float dlt = zr[c] - mu; v += dlt * dlt; }
        v *= (1.f / 128.f);
        muS[tid] = mu;
        rsS[tid] = rsqrtf(v + 1e-5f);
    }
    __syncthreads();

    const float* g = lng + type * 128;
    const float* be = lnb + type * 128;
    float* ob = out + (size_t)type * NN * DD;
#pragma unroll
    for (int i = 0; i < 4; i++) {
        int r = ty * 4 + i;
        int row = m0 + r;
        if (row < NN) {
            float mu = muS[r], rv = rsS[r];
            float o[8];
#pragma unroll
            for (int j = 0; j < 8; j++) {
                int col = tx * 8 + j;
                float z = Us[r * XPITCH + col];
                o[j] = fmaxf((z - mu) * rv * g[col] + be[col], 0.f);
            }
            float4* op = (float4*)(ob + (size_t)row * DD + tx * 8);
            op[0] = make_float4(o[0], o[1], o[2], o[3]);
            op[1] = make_float4(o[4], o[5], o[6], o[7]);
        }
    }
}

// ---------------------------------------------------------------
extern "C" void kernel_launch(void* const* d_in, const int* in_sizes, int n_in,
                              void* d_out, int out_size)
{
    const float* x    = (const float*)d_in[0];
    const int*   ei   = (const int*)d_in[1];
    const float* ea   = (const float*)d_in[2];
    const float* bdW1 = (const float*)d_in[3];
    const float* bdb1 = (const float*)d_in[4];
    const float* bdW2 = (const float*)d_in[5];
    const float* bdb2 = (const float*)d_in[6];
    const float* bdW3 = (const float*)d_in[7];
    const float* bdb3 = (const float*)d_in[8];
    const float* etW1 = (const float*)d_in[9];
    const float* etb1 = (const float*)d_in[10];
    const float* etW2 = (const float*)d_in[11];
    const float* etb2 = (const float*)d_in[12];
    const float* bwW1 = (const float*)d_in[13];
    const float* bwb1 = (const float*)d_in[14];
    const float* bwW2 = (const float*)d_in[15];
    const float* bwb2 = (const float*)d_in[16];
    const float* bwW3 = (const float*)d_in[17];
    const float* bwb3 = (const float*)d_in[18];
    const float* nuW  = (const float*)d_in[19];
    const float* nub  = (const float*)d_in[20];
    const float* lng  = (const float*)d_in[21];
    const float* lnb  = (const float*)d_in[22];
    float* out = (float*)d_out;

    const int SMEM_ET = (TM * XPITCH + 128 * 128) * 4;          // 99328 B
    const int SMEM_NU = (TM * XPITCH + 128 * 128 + 128) * 4;    // 99840 B
    cudaFuncSetAttribute((const void*)et_kernel,
                         cudaFuncAttributeMaxDynamicSharedMemorySize, SMEM_ET);
    cudaFuncSetAttribute((const void*)nu_kernel,
                         cudaFuncAttributeMaxDynamicSharedMemorySize, SMEM_NU);

    init_upd_kernel<<<12500, 256>>>(x);
    boundary_kernel<<<dim3((NN + 127) / 128, 2), 128>>>(x, bdW1, bdb1, bdW2, bdb2, bdW3, bdb3);
    et_kernel<<<dim3((NN + TM - 1) / TM, 2), 256, SMEM_ET>>>(x, etW1, etb1, etW2, etb2);
    coef_kernel<<<dim3((EE + 255) / 256, 2), 256>>>(ei, ea, bwW1, bwb1, bwW2, bwb2, bwW3, bwb3);
    scatter_kernel<<<dim3((EE + 7) / 8, 2), 256>>>(ei);
    nu_kernel<<<dim3((NN + TM - 1) / TM, 2), 256, SMEM_NU>>>(nuW, nub, lng, lnb, out);
}

// round 2
// speedup vs baseline: 1.3663x; 1.3663x over previous
#include <cuda_runtime.h>
#include <cuda_bf16.h>
#include <math.h>

#define NN 50000
#define DD 128
#define EE 800000
#define TM 64
#define XPITCH 132

// -------- device scratch (no runtime allocation allowed) --------
__device__ float g_b[2 * NN];               // boundary scores
__device__ float g_t[2 * (size_t)NN * DD];  // per-type transformed features (51.2MB)
__device__ float g_upd[2 * (size_t)NN * DD];// x + aggregated messages (51.2MB)
__device__ int   g_cnt[2 * NN];             // per-dst incoming-edge count
__device__ int   g_off[2 * NN];             // CSR start offsets
__device__ int   g_cur[2 * NN];             // CSR cursor (ends at end offsets)
__device__ int   g_srcA[2 * (size_t)EE];    // CSR-ordered source node ids
__device__ float g_cvalA[2 * (size_t)EE];   // CSR-ordered edge coefficients

// ---------------------------------------------------------------
// 0) zero histogram counters
// ---------------------------------------------------------------
__global__ void prep_kernel() {
    int i = blockIdx.x * blockDim.x + threadIdx.x;
    if (i < 2 * NN) g_cnt[i] = 0;
}

// ---------------------------------------------------------------
// 0b) histogram of destination nodes per edge type
// ---------------------------------------------------------------
__global__ __launch_bounds__(256) void hist_kernel(const int* __restrict__ ei) {
    int type = blockIdx.y;
    int j = blockIdx.x * 256 + threadIdx.x;
    if (j >= EE) return;
    int d = ei[(size_t)type * 2 * EE + EE + j];
    atomicAdd(&g_cnt[type * NN + d], 1);
}

// ---------------------------------------------------------------
// 0c) exclusive scan per type (one block of 1024 threads per type)
// ---------------------------------------------------------------
__global__ __launch_bounds__(1024) void scan_kernel() {
    __shared__ int warpsums[32];
    __shared__ int carry_s;
    int type = blockIdx.x;
    int tid = threadIdx.x;
    int lane = tid & 31, wid = tid >> 5;
    if (tid == 0) carry_s = 0;
    __syncthreads();

    for (int base = 0; base < NN; base += 1024) {
        int idx = base + tid;
        int v = (idx < NN) ? g_cnt[type * NN + idx] : 0;
        // inclusive warp scan
        int xinc = v;
#pragma unroll
        for (int o = 1; o < 32; o <<= 1) {
            int y = __shfl_up_sync(0xffffffffu, xinc, o);
            if (lane >= o) xinc += y;
        }
        if (lane == 31) warpsums[wid] = xinc;
        __syncthreads();
        if (tid < 32) {
            int w = warpsums[tid];
            int s = w;
#pragma unroll
            for (int o = 1; o < 32; o <<= 1) {
                int y = __shfl_up_sync(0xffffffffu, s, o);
                if (tid >= o) s += y;
            }
            warpsums[tid] = s - w;  // exclusive
        }
        __syncthreads();
        int excl = (xinc - v) + warpsums[wid] + carry_s;
        if (idx < NN) {
            g_off[type * NN + idx] = excl;
            g_cur[type * NN + idx] = excl;
        }
        __syncthreads();
        if (tid == 1023) carry_s = excl + v;
        __syncthreads();
    }
}

// ---------------------------------------------------------------
// 1) boundary MLP: b[t][n] = sigmoid(MLP(x[t][n]))   128->64->32->1
// ---------------------------------------------------------------
__global__ __launch_bounds__(128) void boundary_kernel(
    const float* __restrict__ x,
    const float* __restrict__ bdW1, const float* __restrict__ bdb1,
    const float* __restrict__ bdW2, const float* __restrict__ bdb2,
    const float* __restrict__ bdW3, const float* __restrict__ bdb3)
{
    __shared__ float W1s[128 * 64];
    __shared__ float W2s[64 * 32];
    __shared__ float W3s[32];
    __shared__ float b1s[64], b2s[32];
    __shared__ float b3s;

    int type = blockIdx.y;
    int tid = threadIdx.x;
    const float* W1 = bdW1 + (size_t)type * 128 * 64;
    const float* W2 = bdW2 + (size_t)type * 64 * 32;
    for (int i = tid; i < 128 * 64; i += 128) W1s[i] = W1[i];
    for (int i = tid; i < 64 * 32; i += 128) W2s[i] = W2[i];
    if (tid < 32) W3s[tid] = bdW3[type * 32 + tid];
    if (tid < 64) b1s[tid] = bdb1[type * 64 + tid];
    if (tid < 32) b2s[tid] = bdb2[type * 32 + tid];
    if (tid == 0) b3s = bdb3[type];
    __syncthreads();

    int node = blockIdx.x * 128 + tid;
    if (node >= NN) return;

    const float4* xr = (const float4*)(x + ((size_t)type * NN + node) * DD);

    float h1[64];
#pragma unroll
    for (int j = 0; j < 64; j++) h1[j] = b1s[j];

    for (int d4 = 0; d4 < 32; d4++) {
        float4 xv = xr[d4];
        float vs[4] = {xv.x, xv.y, xv.z, xv.w};
#pragma unroll
        for (int dd = 0; dd < 4; dd++) {
            float v = vs[dd];
            const float4* wr = (const float4*)&W1s[(d4 * 4 + dd) * 64];
#pragma unroll
            for (int q = 0; q < 16; q++) {
                float4 w = wr[q];
                h1[q * 4 + 0] += v * w.x;
                h1[q * 4 + 1] += v * w.y;
                h1[q * 4 + 2] += v * w.z;
                h1[q * 4 + 3] += v * w.w;
            }
        }
    }
#pragma unroll
    for (int j = 0; j < 64; j++) h1[j] = fmaxf(h1[j], 0.f);

    float h2[32];
#pragma unroll
    for (int j = 0; j < 32; j++) h2[j] = b2s[j];
#pragma unroll
    for (int k = 0; k < 64; k++) {
        float v = h1[k];
        const float4* wr = (const float4*)&W2s[k * 32];
#pragma unroll
        for (int q = 0; q < 8; q++) {
            float4 w = wr[q];
            h2[q * 4 + 0] += v * w.x;
            h2[q * 4 + 1] += v * w.y;
            h2[q * 4 + 2] += v * w.z;
            h2[q * 4 + 3] += v * w.w;
        }
    }
    float z = b3s;
#pragma unroll
    for (int k = 0; k < 32; k++) z += fmaxf(h2[k], 0.f) * W3s[k];

    g_b[type * NN + node] = 1.f / (1.f + expf(-z));
}

// ---------------------------------------------------------------
// shared GEMM microkernel: C(64x128) += Xs(64x128) * Ws(128x128)
// ---------------------------------------------------------------
__device__ __forceinline__ void gemm_tile(const float* Xs, const float* Ws,
                                          float acc[4][8], int tx, int ty)
{
#pragma unroll 4
    for (int k = 0; k < 128; k++) {
        float a0 = Xs[(ty * 4 + 0) * XPITCH + k];
        float a1 = Xs[(ty * 4 + 1) * XPITCH + k];
        float a2 = Xs[(ty * 4 + 2) * XPITCH + k];
        float a3 = Xs[(ty * 4 + 3) * XPITCH + k];
        const float4* wp = (const float4*)&Ws[k * 128 + tx * 8];
        float4 w0 = wp[0], w1 = wp[1];
        float wv[8] = {w0.x, w0.y, w0.z, w0.w, w1.x, w1.y, w1.z, w1.w};
#pragma unroll
        for (int j = 0; j < 8; j++) {
            acc[0][j] += a0 * wv[j];
            acc[1][j] += a1 * wv[j];
            acc[2][j] += a2 * wv[j];
            acc[3][j] += a3 * wv[j];
        }
    }
}

// ---------------------------------------------------------------
// 2) edge-type transform: t = relu(x @ W1 + b1) @ W2 + b2
// ---------------------------------------------------------------
__global__ __launch_bounds__(256, 2) void et_kernel(
    const float* __restrict__ x,
    const float* __restrict__ W1g, const float* __restrict__ b1g,
    const float* __restrict__ W2g, const float* __restrict__ b2g)
{
    extern __shared__ float sm[];
    float* Xs = sm;
    float* Ws = sm + TM * XPITCH;

    int type = blockIdx.y;
    int m0 = blockIdx.x * TM;
    int tid = threadIdx.x;
    int tx = tid & 15, ty = tid >> 4;
    const float* xb = x + (size_t)type * NN * DD;

    for (int i = tid; i < TM * 32; i += 256) {
        int r = i >> 5, c4 = i & 31;
        int row = m0 + r;
        float4 v = (row < NN) ? ((const float4*)(xb + (size_t)row * DD))[c4]
                              : make_float4(0.f, 0.f, 0.f, 0.f);
        float* dst = &Xs[r * XPITCH + c4 * 4];
        dst[0] = v.x; dst[1] = v.y; dst[2] = v.z; dst[3] = v.w;
    }
    {
        const float4* W1 = (const float4*)(W1g + (size_t)type * 128 * 128);
        for (int i = tid; i < 128 * 32; i += 256) ((float4*)Ws)[i] = W1[i];
    }
    __syncthreads();

    float acc[4][8];
    {
        const float* b1 = b1g + type * 128 + tx * 8;
#pragma unroll
        for (int j = 0; j < 8; j++) {
            float bv = b1[j];
            acc[0][j] = bv; acc[1][j] = bv; acc[2][j] = bv; acc[3][j] = bv;
        }
    }
    gemm_tile(Xs, Ws, acc, tx, ty);
    __syncthreads();

#pragma unroll
    for (int i = 0; i < 4; i++)
#pragma unroll
        for (int j = 0; j < 8; j++)
            Xs[(ty * 4 + i) * XPITCH + tx * 8 + j] = fmaxf(acc[i][j], 0.f);
    {
        const float4* W2 = (const float4*)(W2g + (size_t)type * 128 * 128);
        for (int i = tid; i < 128 * 32; i += 256) ((float4*)Ws)[i] = W2[i];
    }
    __syncthreads();

    {
        const float* b2 = b2g + type * 128 + tx * 8;
#pragma unroll
        for (int j = 0; j < 8; j++) {
            float bv = b2[j];
            acc[0][j] = bv; acc[1][j] = bv; acc[2][j] = bv; acc[3][j] = bv;
        }
    }
    gemm_tile(Xs, Ws, acc, tx, ty);

    float* tb = g_t + (size_t)type * NN * DD;
#pragma unroll
    for (int i = 0; i < 4; i++) {
        int row = m0 + ty * 4 + i;
        if (row < NN) {
            float4* op = (float4*)(tb + (size_t)row * DD + tx * 8);
            op[0] = make_float4(acc[i][0], acc[i][1], acc[i][2], acc[i][3]);
            op[1] = make_float4(acc[i][4], acc[i][5], acc[i][6], acc[i][7]);
        }
    }
}

// ---------------------------------------------------------------
// 3) per-edge coefficient MLP + CSR binning (fused)
// ---------------------------------------------------------------
__global__ __launch_bounds__(256) void coef_order_kernel(
    const int* __restrict__ ei, const float* __restrict__ ea,
    const float* __restrict__ bwW1, const float* __restrict__ bwb1,
    const float* __restrict__ bwW2, const float* __restrict__ bwb2,
    const float* __restrict__ bwW3, const float* __restrict__ bwb3)
{
    __shared__ float W1s[64], B1s[32], W2s[512], B2s[16], W3s[16];
    __shared__ float B3s;
    int type = blockIdx.y;
    int tid = threadIdx.x;
    if (tid < 64) W1s[tid] = bwW1[type * 64 + tid];
    if (tid < 32) B1s[tid] = bwb1[type * 32 + tid];
    for (int i = tid; i < 512; i += 256) W2s[i] = bwW2[type * 512 + i];
    if (tid < 16) B2s[tid] = bwb2[type * 16 + tid];
    if (tid < 16) W3s[tid] = bwW3[type * 16 + tid];
    if (tid == 0) B3s = bwb3[type];
    __syncthreads();

    int j = blockIdx.x * 256 + tid;
    if (j >= EE) return;
    const int* eib = ei + (size_t)type * 2 * EE;
    int s = eib[j];
    int d = eib[EE + j];
    float sb = g_b[type * NN + s];
    float db = g_b[(1 - type) * NN + d];

    float h1[32];
#pragma unroll
    for (int q = 0; q < 32; q++)
        h1[q] = fmaxf(sb * W1s[q] + db * W1s[32 + q] + B1s[q], 0.f);

    float4 h2v[4];
#pragma unroll
    for (int p = 0; p < 4; p++) h2v[p] = ((const float4*)B2s)[p];
    const float4* W2v = (const float4*)W2s;
#pragma unroll
    for (int q = 0; q < 32; q++) {
        float v = h1[q];
#pragma unroll
        for (int p = 0; p < 4; p++) {
            float4 w = W2v[q * 4 + p];
            h2v[p].x += v * w.x;
            h2v[p].y += v * w.y;
            h2v[p].z += v * w.z;
            h2v[p].w += v * w.w;
        }
    }
    float z = B3s;
#pragma unroll
    for (int p = 0; p < 4; p++) {
        z += fmaxf(h2v[p].x, 0.f) * W3s[p * 4 + 0];
        z += fmaxf(h2v[p].y, 0.f) * W3s[p * 4 + 1];
        z += fmaxf(h2v[p].z, 0.f) * W3s[p * 4 + 2];
        z += fmaxf(h2v[p].w, 0.f) * W3s[p * 4 + 3];
    }

    float w = 1.f / (1.f + expf(-z));
    if (sb > 0.3f || db > 0.3f) w *= 2.f;
    float c = ea[(size_t)type * EE + j] * w;

    int pos = atomicAdd(&g_cur[type * NN + d], 1);
    g_srcA[(size_t)type * EE + pos] = s;
    g_cvalA[(size_t)type * EE + pos] = c;
}

// ---------------------------------------------------------------
// 4) gather: upd[to][n] = x[to][n] + sum over CSR(type e=1-to, dst n)
//    warp per destination node, lane owns one float4 column chunk
// ---------------------------------------------------------------
__global__ __launch_bounds__(256) void gather_kernel(const float* __restrict__ x)
{
    int to = blockIdx.y;            // output node type
    int e = 1 - to;                 // edge type landing on this node type
    int lane = threadIdx.x & 31;
    int warp = threadIdx.x >> 5;
    int n = blockIdx.x * 8 + warp;
    if (n >= NN) return;

    int base = e * NN + n;
    int st = g_off[base];
    int en = g_cur[base];

    const float4* tb = (const float4*)(g_t + (size_t)e * NN * DD);
    const int* srcp = g_srcA + (size_t)e * EE;
    const float* cvp = g_cvalA + (size_t)e * EE;

    float4 acc = ((const float4*)(x + ((size_t)to * NN + n) * DD))[lane];

    int i = st;
    for (; i + 1 < en; i += 2) {
        int s0 = srcp[i], s1 = srcp[i + 1];
        float c0 = cvp[i], c1 = cvp[i + 1];
        float4 v0 = tb[(size_t)s0 * 32 + lane];
        float4 v1 = tb[(size_t)s1 * 32 + lane];
        acc.x += v0.x * c0; acc.y += v0.y * c0; acc.z += v0.z * c0; acc.w += v0.w * c0;
        acc.x += v1.x * c1; acc.y += v1.y * c1; acc.z += v1.z * c1; acc.w += v1.w * c1;
    }
    if (i < en) {
        int s0 = srcp[i];
        float c0 = cvp[i];
        float4 v0 = tb[(size_t)s0 * 32 + lane];
        acc.x += v0.x * c0; acc.y += v0.y * c0; acc.z += v0.z * c0; acc.w += v0.w * c0;
    }

    ((float4*)(g_upd + ((size_t)to * NN + n) * DD))[lane] = acc;
}

// ---------------------------------------------------------------
// 5) node update: out = relu(LN(upd @ nuW + nub) * g + b)
// ---------------------------------------------------------------
__global__ __launch_bounds__(256, 2) void nu_kernel(
    const float* __restrict__ nuW, const float* __restrict__ nub,
    const float* __restrict__ lng, const float* __restrict__ lnb,
    float* __restrict__ out)
{
    extern __shared__ float sm[];
    float* Us = sm;
    float* Ws = sm + TM * XPITCH;
    float* muS = Ws + 128 * 128;
    float* rsS = muS + 64;

    int type = blockIdx.y;
    int m0 = blockIdx.x * TM;
    int tid = threadIdx.x;
    int tx = tid & 15, ty = tid >> 4;
    const float* ub = g_upd + (size_t)type * NN * DD;

    for (int i = tid; i < TM * 32; i += 256) {
        int r = i >> 5, c4 = i & 31;
        int row = m0 + r;
        float4 v = (row < NN) ? ((const float4*)(ub + (size_t)row * DD))[c4]
                              : make_float4(0.f, 0.f, 0.f, 0.f);
        float* dst = &Us[r * XPITCH + c4 * 4];
        dst[0] = v.x; dst[1] = v.y; dst[2] = v.z; dst[3] = v.w;
    }
    {
        const float4* W = (const float4*)(nuW + (size_t)type * 128 * 128);
        for (int i = tid; i < 128 * 32; i += 256) ((float4*)Ws)[i] = W[i];
    }
    __syncthreads();

    float acc[4][8];
    {
        const float* bb = nub + type * 128 + tx * 8;
#pragma unroll
        for (int j = 0; j < 8; j++) {
            float bv = bb[j];
            acc[0][j] = bv; acc[1][j] = bv; acc[2][j] = bv; acc[3][j] = bv;
        }
    }
    gemm_tile(Us, Ws, acc, tx, ty);
    __syncthreads();

#pragma unroll
    for (int i = 0; i < 4; i++)
#pragma unroll
        for (int j = 0; j < 8; j++)
            Us[(ty * 4 + i) * XPITCH + tx * 8 + j] = acc[i][j];
    __syncthreads();

    if (tid < 64) {
        const float* zr = &Us[tid * XPITCH];
        float s = 0.f;
        for (int c = 0; c < 128; c++) s += zr[c];
        float mu = s * (1.f / 128.f);
        float v = 0.f;
        for (int c = 0; c < 128; c++) { float dlt = zr[c] - mu; v += dlt * dlt; }
        v *= (1.f / 128.f);
        muS[tid] = mu;
        rsS[tid] = rsqrtf(v + 1e-5f);
    }
    __syncthreads();

    const float* g = lng + type * 128;
    const float* be = lnb + type * 128;
    float* ob = out + (size_t)type * NN * DD;
#pragma unroll
    for (int i = 0; i < 4; i++) {
        int r = ty * 4 + i;
        int row = m0 + r;
        if (row < NN) {
            float mu = muS[r], rv = rsS[r];
            float o[8];
#pragma unroll
            for (int j = 0; j < 8; j++) {
                int col = tx * 8 + j;
                float z = Us[r * XPITCH + col];
                o[j] = fmaxf((z - mu) * rv * g[col] + be[col], 0.f);
            }
            float4* op = (float4*)(ob + (size_t)row * DD + tx * 8);
            op[0] = make_float4(o[0], o[1], o[2], o[3]);
            op[1] = make_float4(o[4], o[5], o[6], o[7]);
        }
    }
}

// ---------------------------------------------------------------
extern "C" void kernel_launch(void* const* d_in, const int* in_sizes, int n_in,
                              void* d_out, int out_size)
{
    const float* x    = (const float*)d_in[0];
    const int*   ei   = (const int*)d_in[1];
    const float* ea   = (const float*)d_in[2];
    const float* bdW1 = (const float*)d_in[3];
    const float* bdb1 = (const float*)d_in[4];
    const float* bdW2 = (const float*)d_in[5];
    const float* bdb2 = (const float*)d_in[6];
    const float* bdW3 = (const float*)d_in[7];
    const float* bdb3 = (const float*)d_in[8];
    const float* etW1 = (const float*)d_in[9];
    const float* etb1 = (const float*)d_in[10];
    const float* etW2 = (const float*)d_in[11];
    const float* etb2 = (const float*)d_in[12];
    const float* bwW1 = (const float*)d_in[13];
    const float* bwb1 = (const float*)d_in[14];
    const float* bwW2 = (const float*)d_in[15];
    const float* bwb2 = (const float*)d_in[16];
    const float* bwW3 = (const float*)d_in[17];
    const float* bwb3 = (const float*)d_in[18];
    const float* nuW  = (const float*)d_in[19];
    const float* nub  = (const float*)d_in[20];
    const float* lng  = (const float*)d_in[21];
    const float* lnb  = (const float*)d_in[22];
    float* out = (float*)d_out;

    const int SMEM_ET = (TM * XPITCH + 128 * 128) * 4;
    const int SMEM_NU = (TM * XPITCH + 128 * 128 + 128) * 4;
    cudaFuncSetAttribute((const void*)et_kernel,
                         cudaFuncAttributeMaxDynamicSharedMemorySize, SMEM_ET);
    cudaFuncSetAttribute((const void*)nu_kernel,
                         cudaFuncAttributeMaxDynamicSharedMemorySize, SMEM_NU);

    prep_kernel<<<(2 * NN + 255) / 256, 256>>>();
    hist_kernel<<<dim3((EE + 255) / 256, 2), 256>>>(ei);
    boundary_kernel<<<dim3((NN + 127) / 128, 2), 128>>>(x, bdW1, bdb1, bdW2, bdb2, bdW3, bdb3);
    scan_kernel<<<2, 1024>>>();
    et_kernel<<<dim3((NN + TM - 1) / TM, 2), 256, SMEM_ET>>>(x, etW1, etb1, etW2, etb2);
    coef_order_kernel<<<dim3((EE + 255) / 256, 2), 256>>>(ei, ea, bwW1, bwb1, bwW2, bwb2, bwW3, bwb3);
    gather_kernel<<<dim3((NN + 7) / 8, 2), 256>>>(x);
    nu_kernel<<<dim3((NN + TM - 1) / TM, 2), 256, SMEM_NU>>>(nuW, nub, lng, lnb, out);
}

// round 3
// speedup vs baseline: 1.5311x; 1.1206x over previous
#include <cuda_runtime.h>
#include <cuda_bf16.h>
#include <math.h>

#define NN 50000
#define DD 128
#define EE 800000
#define TM 64
#define XPITCH 132
#define NCHUNK 49   // ceil(50000/1024)

// -------- device scratch (no runtime allocation allowed) --------
__device__ float g_b[2 * NN];               // boundary scores
__device__ float g_t[2 * (size_t)NN * DD];  // per-type transformed features
__device__ float g_upd[2 * (size_t)NN * DD];// x + aggregated messages
__device__ int   g_cnt[2 * NN];             // per-dst incoming-edge count
__device__ int   g_off[2 * NN];             // CSR start offsets
__device__ int   g_cur[2 * NN];             // CSR cursor (ends at end offsets)
__device__ int   g_bsum[2 * 64];            // per-chunk block sums for scan
__device__ int   g_srcA[2 * (size_t)EE];    // CSR-ordered source node ids
__device__ float g_cvalA[2 * (size_t)EE];   // CSR-ordered edge coefficients

// ---------------------------------------------------------------
// 0) zero histogram counters
// ---------------------------------------------------------------
__global__ void prep_kernel() {
    int i = blockIdx.x * blockDim.x + threadIdx.x;
    if (i < 2 * NN) g_cnt[i] = 0;
}

// ---------------------------------------------------------------
// 0b) histogram of destination nodes per edge type
// ---------------------------------------------------------------
__global__ __launch_bounds__(256) void hist_kernel(const int* __restrict__ ei) {
    int type = blockIdx.y;
    int j = blockIdx.x * 256 + threadIdx.x;
    if (j >= EE) return;
    int d = ei[(size_t)type * 2 * EE + EE + j];
    atomicAdd(&g_cnt[type * NN + d], 1);
}

// ---------------------------------------------------------------
// 0c) decoupled 3-phase exclusive scan
// ---------------------------------------------------------------
__global__ __launch_bounds__(1024) void scan1_kernel() {
    __shared__ int warpsums[32];
    int type = blockIdx.y, chunk = blockIdx.x;
    int tid = threadIdx.x, lane = tid & 31, wid = tid >> 5;
    int idx = chunk * 1024 + tid;
    int v = (idx < NN) ? g_cnt[type * NN + idx] : 0;
    int inc = v;
#pragma unroll
    for (int o = 1; o < 32; o <<= 1) {
        int y = __shfl_up_sync(0xffffffffu, inc, o);
        if (lane >= o) inc += y;
    }
    if (lane == 31) warpsums[wid] = inc;
    __syncthreads();
    if (tid < 32) {
        int w = warpsums[tid];
        int s = w;
#pragma unroll
        for (int o = 1; o < 32; o <<= 1) {
            int y = __shfl_up_sync(0xffffffffu, s, o);
            if (tid >= o) s += y;
        }
        warpsums[tid] = s - w;
    }
    __syncthreads();
    int excl = inc - v + warpsums[wid];
    if (idx < NN) g_off[type * NN + idx] = excl;
    if (tid == 1023) g_bsum[type * 64 + chunk] = excl + v;
}

__global__ void scan2_kernel() {
    int type = threadIdx.x;
    if (type < 2) {
        int run = 0;
        for (int c = 0; c < NCHUNK; c++) {
            int v = g_bsum[type * 64 + c];
            g_bsum[type * 64 + c] = run;
            run += v;
        }
    }
}

__global__ __launch_bounds__(1024) void scan3_kernel() {
    int type = blockIdx.y, chunk = blockIdx.x;
    int idx = chunk * 1024 + threadIdx.x;
    if (idx < NN) {
        int o = g_off[type * NN + idx] + g_bsum[type * 64 + chunk];
        g_off[type * NN + idx] = o;
        g_cur[type * NN + idx] = o;
    }
}

// ---------------------------------------------------------------
// 1) boundary MLP: b[t][n] = sigmoid(MLP(x[t][n]))   128->64->32->1
// ---------------------------------------------------------------
__global__ __launch_bounds__(128) void boundary_kernel(
    const float* __restrict__ x,
    const float* __restrict__ bdW1, const float* __restrict__ bdb1,
    const float* __restrict__ bdW2, const float* __restrict__ bdb2,
    const float* __restrict__ bdW3, const float* __restrict__ bdb3)
{
    __shared__ float W1s[128 * 64];
    __shared__ float W2s[64 * 32];
    __shared__ float W3s[32];
    __shared__ float b1s[64], b2s[32];
    __shared__ float b3s;

    int type = blockIdx.y;
    int tid = threadIdx.x;
    const float* W1 = bdW1 + (size_t)type * 128 * 64;
    const float* W2 = bdW2 + (size_t)type * 64 * 32;
    for (int i = tid; i < 128 * 64; i += 128) W1s[i] = W1[i];
    for (int i = tid; i < 64 * 32; i += 128) W2s[i] = W2[i];
    if (tid < 32) W3s[tid] = bdW3[type * 32 + tid];
    if (tid < 64) b1s[tid] = bdb1[type * 64 + tid];
    if (tid < 32) b2s[tid] = bdb2[type * 32 + tid];
    if (tid == 0) b3s = bdb3[type];
    __syncthreads();

    int node = blockIdx.x * 128 + tid;
    if (node >= NN) return;

    const float4* xr = (const float4*)(x + ((size_t)type * NN + node) * DD);

    float h1[64];
#pragma unroll
    for (int j = 0; j < 64; j++) h1[j] = b1s[j];

    for (int d4 = 0; d4 < 32; d4++) {
        float4 xv = xr[d4];
        float vs[4] = {xv.x, xv.y, xv.z, xv.w};
#pragma unroll
        for (int dd = 0; dd < 4; dd++) {
            float v = vs[dd];
            const float4* wr = (const float4*)&W1s[(d4 * 4 + dd) * 64];
#pragma unroll
            for (int q = 0; q < 16; q++) {
                float4 w = wr[q];
                h1[q * 4 + 0] += v * w.x;
                h1[q * 4 + 1] += v * w.y;
                h1[q * 4 + 2] += v * w.z;
                h1[q * 4 + 3] += v * w.w;
            }
        }
    }
#pragma unroll
    for (int j = 0; j < 64; j++) h1[j] = fmaxf(h1[j], 0.f);

    float h2[32];
#pragma unroll
    for (int j = 0; j < 32; j++) h2[j] = b2s[j];
#pragma unroll
    for (int k = 0; k < 64; k++) {
        float v = h1[k];
        const float4* wr = (const float4*)&W2s[k * 32];
#pragma unroll
        for (int q = 0; q < 8; q++) {
            float4 w = wr[q];
            h2[q * 4 + 0] += v * w.x;
            h2[q * 4 + 1] += v * w.y;
            h2[q * 4 + 2] += v * w.z;
            h2[q * 4 + 3] += v * w.w;
        }
    }
    float z = b3s;
#pragma unroll
    for (int k = 0; k < 32; k++) z += fmaxf(h2[k], 0.f) * W3s[k];

    g_b[type * NN + node] = 1.f / (1.f + expf(-z));
}

// ---------------------------------------------------------------
// shared GEMM microkernel: C(64x128) += Xs(64x128) * Ws(128x128)
// ---------------------------------------------------------------
__device__ __forceinline__ void gemm_tile(const float* Xs, const float* Ws,
                                          float acc[4][8], int tx, int ty)
{
#pragma unroll 4
    for (int k = 0; k < 128; k++) {
        float a0 = Xs[(ty * 4 + 0) * XPITCH + k];
        float a1 = Xs[(ty * 4 + 1) * XPITCH + k];
        float a2 = Xs[(ty * 4 + 2) * XPITCH + k];
        float a3 = Xs[(ty * 4 + 3) * XPITCH + k];
        const float4* wp = (const float4*)&Ws[k * 128 + tx * 8];
        float4 w0 = wp[0], w1 = wp[1];
        float wv[8] = {w0.x, w0.y, w0.z, w0.w, w1.x, w1.y, w1.z, w1.w};
#pragma unroll
        for (int j = 0; j < 8; j++) {
            acc[0][j] += a0 * wv[j];
            acc[1][j] += a1 * wv[j];
            acc[2][j] += a2 * wv[j];
            acc[3][j] += a3 * wv[j];
        }
    }
}

// ---------------------------------------------------------------
// 2) edge-type transform: t = relu(x @ W1 + b1) @ W2 + b2
// ---------------------------------------------------------------
__global__ __launch_bounds__(256, 2) void et_kernel(
    const float* __restrict__ x,
    const float* __restrict__ W1g, const float* __restrict__ b1g,
    const float* __restrict__ W2g, const float* __restrict__ b2g)
{
    extern __shared__ float sm[];
    float* Xs = sm;
    float* Ws = sm + TM * XPITCH;

    int type = blockIdx.y;
    int m0 = blockIdx.x * TM;
    int tid = threadIdx.x;
    int tx = tid & 15, ty = tid >> 4;
    const float* xb = x + (size_t)type * NN * DD;

    for (int i = tid; i < TM * 32; i += 256) {
        int r = i >> 5, c4 = i & 31;
        int row = m0 + r;
        float4 v = (row < NN) ? ((const float4*)(xb + (size_t)row * DD))[c4]
                              : make_float4(0.f, 0.f, 0.f, 0.f);
        float* dst = &Xs[r * XPITCH + c4 * 4];
        dst[0] = v.x; dst[1] = v.y; dst[2] = v.z; dst[3] = v.w;
    }
    {
        const float4* W1 = (const float4*)(W1g + (size_t)type * 128 * 128);
        for (int i = tid; i < 128 * 32; i += 256) ((float4*)Ws)[i] = W1[i];
    }
    __syncthreads();

    float acc[4][8];
    {
        const float* b1 = b1g + type * 128 + tx * 8;
#pragma unroll
        for (int j = 0; j < 8; j++) {
            float bv = b1[j];
            acc[0][j] = bv; acc[1][j] = bv; acc[2][j] = bv; acc[3][j] = bv;
        }
    }
    gemm_tile(Xs, Ws, acc, tx, ty);
    __syncthreads();

#pragma unroll
    for (int i = 0; i < 4; i++)
#pragma unroll
        for (int j = 0; j < 8; j++)
            Xs[(ty * 4 + i) * XPITCH + tx * 8 + j] = fmaxf(acc[i][j], 0.f);
    {
        const float4* W2 = (const float4*)(W2g + (size_t)type * 128 * 128);
        for (int i = tid; i < 128 * 32; i += 256) ((float4*)Ws)[i] = W2[i];
    }
    __syncthreads();

    {
        const float* b2 = b2g + type * 128 + tx * 8;
#pragma unroll
        for (int j = 0; j < 8; j++) {
            float bv = b2[j];
            acc[0][j] = bv; acc[1][j] = bv; acc[2][j] = bv; acc[3][j] = bv;
        }
    }
    gemm_tile(Xs, Ws, acc, tx, ty);

    float* tb = g_t + (size_t)type * NN * DD;
#pragma unroll
    for (int i = 0; i < 4; i++) {
        int row = m0 + ty * 4 + i;
        if (row < NN) {
            float4* op = (float4*)(tb + (size_t)row * DD + tx * 8);
            op[0] = make_float4(acc[i][0], acc[i][1], acc[i][2], acc[i][3]);
            op[1] = make_float4(acc[i][4], acc[i][5], acc[i][6], acc[i][7]);
        }
    }
}

// ---------------------------------------------------------------
// 3) per-edge coefficient MLP + CSR binning (fused)
// ---------------------------------------------------------------
__global__ __launch_bounds__(256) void coef_order_kernel(
    const int* __restrict__ ei, const float* __restrict__ ea,
    const float* __restrict__ bwW1, const float* __restrict__ bwb1,
    const float* __restrict__ bwW2, const float* __restrict__ bwb2,
    const float* __restrict__ bwW3, const float* __restrict__ bwb3)
{
    __shared__ float W1s[64], B1s[32], W2s[512], B2s[16], W3s[16];
    __shared__ float B3s;
    int type = blockIdx.y;
    int tid = threadIdx.x;
    if (tid < 64) W1s[tid] = bwW1[type * 64 + tid];
    if (tid < 32) B1s[tid] = bwb1[type * 32 + tid];
    for (int i = tid; i < 512; i += 256) W2s[i] = bwW2[type * 512 + i];
    if (tid < 16) B2s[tid] = bwb2[type * 16 + tid];
    if (tid < 16) W3s[tid] = bwW3[type * 16 + tid];
    if (tid == 0) B3s = bwb3[type];
    __syncthreads();

    int j = blockIdx.x * 256 + tid;
    if (j >= EE) return;
    const int* eib = ei + (size_t)type * 2 * EE;
    int s = eib[j];
    int d = eib[EE + j];
    float sb = g_b[type * NN + s];
    float db = g_b[(1 - type) * NN + d];

    float h1[32];
#pragma unroll
    for (int q = 0; q < 32; q++)
        h1[q] = fmaxf(sb * W1s[q] + db * W1s[32 + q] + B1s[q], 0.f);

    float4 h2v[4];
#pragma unroll
    for (int p = 0; p < 4; p++) h2v[p] = ((const float4*)B2s)[p];
    const float4* W2v = (const float4*)W2s;
#pragma unroll
    for (int q = 0; q < 32; q++) {
        float v = h1[q];
#pragma unroll
        for (int p = 0; p < 4; p++) {
            float4 w = W2v[q * 4 + p];
            h2v[p].x += v * w.x;
            h2v[p].y += v * w.y;
            h2v[p].z += v * w.z;
            h2v[p].w += v * w.w;
        }
    }
    float z = B3s;
#pragma unroll
    for (int p = 0; p < 4; p++) {
        z += fmaxf(h2v[p].x, 0.f) * W3s[p * 4 + 0];
        z += fmaxf(h2v[p].y, 0.f) * W3s[p * 4 + 1];
        z += fmaxf(h2v[p].z, 0.f) * W3s[p * 4 + 2];
        z += fmaxf(h2v[p].w, 0.f) * W3s[p * 4 + 3];
    }

    float w = 1.f / (1.f + expf(-z));
    if (sb > 0.3f || db > 0.3f) w *= 2.f;
    float c = ea[(size_t)type * EE + j] * w;

    int pos = atomicAdd(&g_cur[type * NN + d], 1);
    g_srcA[(size_t)type * EE + pos] = s;
    g_cvalA[(size_t)type * EE + pos] = c;
}

// ---------------------------------------------------------------
// 4) gather: upd[to][n] = x[to][n] + sum over CSR(type e=1-to, dst n)
//    warp per destination node, 4-way unrolled for MLP
// ---------------------------------------------------------------
__global__ __launch_bounds__(256) void gather_kernel(const float* __restrict__ x)
{
    int to = blockIdx.y;            // output node type
    int e = 1 - to;                 // edge type landing on this node type
    int lane = threadIdx.x & 31;
    int warp = threadIdx.x >> 5;
    int n = blockIdx.x * 8 + warp;
    if (n >= NN) return;

    int base = e * NN + n;
    int st = g_off[base];
    int en = g_cur[base];

    const float4* tb = (const float4*)(g_t + (size_t)e * NN * DD);
    const int* srcp = g_srcA + (size_t)e * EE;
    const float* cvp = g_cvalA + (size_t)e * EE;

    float4 acc = ((const float4*)(x + ((size_t)to * NN + n) * DD))[lane];

    int i = st;
    for (; i + 3 < en; i += 4) {
        int s0 = __ldg(srcp + i),     s1 = __ldg(srcp + i + 1);
        int s2 = __ldg(srcp + i + 2), s3 = __ldg(srcp + i + 3);
        float c0 = __ldg(cvp + i),     c1 = __ldg(cvp + i + 1);
        float c2 = __ldg(cvp + i + 2), c3 = __ldg(cvp + i + 3);
        float4 v0 = tb[(size_t)s0 * 32 + lane];
        float4 v1 = tb[(size_t)s1 * 32 + lane];
        float4 v2 = tb[(size_t)s2 * 32 + lane];
        float4 v3 = tb[(size_t)s3 * 32 + lane];
        acc.x += v0.x * c0; acc.y += v0.y * c0; acc.z += v0.z * c0; acc.w += v0.w * c0;
        acc.x += v1.x * c1; acc.y += v1.y * c1; acc.z += v1.z * c1; acc.w += v1.w * c1;
        acc.x += v2.x * c2; acc.y += v2.y * c2; acc.z += v2.z * c2; acc.w += v2.w * c2;
        acc.x += v3.x * c3; acc.y += v3.y * c3; acc.z += v3.z * c3; acc.w += v3.w * c3;
    }
    for (; i < en; i++) {
        int s0 = __ldg(srcp + i);
        float c0 = __ldg(cvp + i);
        float4 v0 = tb[(size_t)s0 * 32 + lane];
        acc.x += v0.x * c0; acc.y += v0.y * c0; acc.z += v0.z * c0; acc.w += v0.w * c0;
    }

    ((float4*)(g_upd + ((size_t)to * NN + n) * DD))[lane] = acc;
}

// ---------------------------------------------------------------
// 5) node update: out = relu(LN(upd @ nuW + nub) * g + b)
// ---------------------------------------------------------------
__global__ __launch_bounds__(256, 2) void nu_kernel(
    const float* __restrict__ nuW, const float* __restrict__ nub,
    const float* __restrict__ lng, const float* __restrict__ lnb,
    float* __restrict__ out)
{
    extern __shared__ float sm[];
    float* Us = sm;
    float* Ws = sm + TM * XPITCH;
    float* muS = Ws + 128 * 128;
    float* rsS = muS + 64;

    int type = blockIdx.y;
    int m0 = blockIdx.x * TM;
    int tid = threadIdx.x;
    int tx = tid & 15, ty = tid >> 4;
    const float* ub = g_upd + (size_t)type * NN * DD;

    for (int i = tid; i < TM * 32; i += 256) {
        int r = i >> 5, c4 = i & 31;
        int row = m0 + r;
        float4 v = (row < NN) ? ((const float4*)(ub + (size_t)row * DD))[c4]
                              : make_float4(0.f, 0.f, 0.f, 0.f);
        float* dst = &Us[r * XPITCH + c4 * 4];
        dst[0] = v.x; dst[1] = v.y; dst[2] = v.z; dst[3] = v.w;
    }
    {
        const float4* W = (const float4*)(nuW + (size_t)type * 128 * 128);
        for (int i = tid; i < 128 * 32; i += 256) ((float4*)Ws)[i] = W[i];
    }
    __syncthreads();

    float acc[4][8];
    {
        const float* bb = nub + type * 128 + tx * 8;
#pragma unroll
        for (int j = 0; j < 8; j++) {
            float bv = bb[j];
            acc[0][j] = bv; acc[1][j] = bv; acc[2][j] = bv; acc[3][j] = bv;
        }
    }
    gemm_tile(Us, Ws, acc, tx, ty);
    __syncthreads();

#pragma unroll
    for (int i = 0; i < 4; i++)
#pragma unroll
        for (int j = 0; j < 8; j++)
            Us[(ty * 4 + i) * XPITCH + tx * 8 + j] = acc[i][j];
    __syncthreads();

    if (tid < 64) {
        const float* zr = &Us[tid * XPITCH];
        float s = 0.f;
        for (int c = 0; c < 128; c++) s += zr[c];
        float mu = s * (1.f / 128.f);
        float v = 0.f;
        for (int c = 0; c < 128; c++) { float dlt = zr[c] - mu; v += dlt * dlt; }
        v *= (1.f / 128.f);
        muS[tid] = mu;
        rsS[tid] = rsqrtf(v + 1e-5f);
    }
    __syncthreads();

    const float* g = lng + type * 128;
    const float* be = lnb + type * 128;
    float* ob = out + (size_t)type * NN * DD;
#pragma unroll
    for (int i = 0; i < 4; i++) {
        int r = ty * 4 + i;
        int row = m0 + r;
        if (row < NN) {
            float mu = muS[r], rv = rsS[r];
            float o[8];
#pragma unroll
            for (int j = 0; j < 8; j++) {
                int col = tx * 8 + j;
                float z = Us[r * XPITCH + col];
                o[j] = fmaxf((z - mu) * rv * g[col] + be[col], 0.f);
            }
            float4* op = (float4*)(ob + (size_t)row * DD + tx * 8);
            op[0] = make_float4(o[0], o[1], o[2], o[3]);
            op[1] = make_float4(o[4], o[5], o[6], o[7]);
        }
    }
}

// ---------------------------------------------------------------
extern "C" void kernel_launch(void* const* d_in, const int* in_sizes, int n_in,
                              void* d_out, int out_size)
{
    const float* x    = (const float*)d_in[0];
    const int*   ei   = (const int*)d_in[1];
    const float* ea   = (const float*)d_in[2];
    const float* bdW1 = (const float*)d_in[3];
    const float* bdb1 = (const float*)d_in[4];
    const float* bdW2 = (const float*)d_in[5];
    const float* bdb2 = (const float*)d_in[6];
    const float* bdW3 = (const float*)d_in[7];
    const float* bdb3 = (const float*)d_in[8];
    const float* etW1 = (const float*)d_in[9];
    const float* etb1 = (const float*)d_in[10];
    const float* etW2 = (const float*)d_in[11];
    const float* etb2 = (const float*)d_in[12];
    const float* bwW1 = (const float*)d_in[13];
    const float* bwb1 = (const float*)d_in[14];
    const float* bwW2 = (const float*)d_in[15];
    const float* bwb2 = (const float*)d_in[16];
    const float* bwW3 = (const float*)d_in[17];
    const float* bwb3 = (const float*)d_in[18];
    const float* nuW  = (const float*)d_in[19];
    const float* nub  = (const float*)d_in[20];
    const float* lng  = (const float*)d_in[21];
    const float* lnb  = (const float*)d_in[22];
    float* out = (float*)d_out;

    const int SMEM_ET = (TM * XPITCH + 128 * 128) * 4;
    const int SMEM_NU = (TM * XPITCH + 128 * 128 + 128) * 4;
    cudaFuncSetAttribute((const void*)et_kernel,
                         cudaFuncAttributeMaxDynamicSharedMemorySize, SMEM_ET);
    cudaFuncSetAttribute((const void*)nu_kernel,
                         cudaFuncAttributeMaxDynamicSharedMemorySize, SMEM_NU);

    prep_kernel<<<(2 * NN + 255) / 256, 256>>>();
    hist_kernel<<<dim3((EE + 255) / 256, 2), 256>>>(ei);
    boundary_kernel<<<dim3((NN + 127) / 128, 2), 128>>>(x, bdW1, bdb1, bdW2, bdb2, bdW3, bdb3);
    scan1_kernel<<<dim3(NCHUNK, 2), 1024>>>();
    scan2_kernel<<<1, 32>>>();
    scan3_kernel<<<dim3(NCHUNK, 2), 1024>>>();
    et_kernel<<<dim3((NN + TM - 1) / TM, 2), 256, SMEM_ET>>>(x, etW1, etb1, etW2, etb2);
    coef_order_kernel<<<dim3((EE + 255) / 256, 2), 256>>>(ei, ea, bwW1, bwb1, bwW2, bwb2, bwW3, bwb3);
    gather_kernel<<<dim3((NN + 7) / 8, 2), 256>>>(x);
    nu_kernel<<<dim3((NN + TM - 1) / TM, 2), 256, SMEM_NU>>>(nuW, nub, lng, lnb, out);
}

// round 4
// speedup vs baseline: 1.5848x; 1.0350x over previous
#include <cuda_runtime.h>
#include <cuda_fp16.h>
#include <cuda_bf16.h>
#include <math.h>

#define NN 50000
#define DD 128
#define EE 800000
#define TM 64
#define XPITCH 132
#define NCHUNK 49   // ceil(50000/1024)

// -------- device scratch (no runtime allocation allowed) --------
__device__ float  g_b[2 * NN];               // boundary scores
__device__ __half g_t[2 * (size_t)NN * DD];  // transformed features (fp16, 25.6MB)
__device__ float  g_upd[2 * (size_t)NN * DD];// x + aggregated messages
__device__ int    g_cnt[2 * NN];             // per-dst incoming-edge count
__device__ int    g_off[2 * NN];             // CSR start offsets
__device__ int    g_cur[2 * NN];             // CSR cursor
__device__ int    g_bsum[2 * 64];            // per-chunk block sums for scan
__device__ int    g_srcA[2 * (size_t)EE];    // CSR-ordered source node ids
__device__ float  g_cvalA[2 * (size_t)EE];   // CSR-ordered edge coefficients

// ---------------------------------------------------------------
__global__ void prep_kernel() {
    int i = blockIdx.x * blockDim.x + threadIdx.x;
    if (i < 2 * NN) g_cnt[i] = 0;
}

__global__ __launch_bounds__(256) void hist_kernel(const int* __restrict__ ei) {
    int type = blockIdx.y;
    int j = blockIdx.x * 256 + threadIdx.x;
    if (j >= EE) return;
    int d = ei[(size_t)type * 2 * EE + EE + j];
    atomicAdd(&g_cnt[type * NN + d], 1);
}

// ---------------------------------------------------------------
// decoupled 3-phase exclusive scan
// ---------------------------------------------------------------
__global__ __launch_bounds__(1024) void scan1_kernel() {
    __shared__ int warpsums[32];
    int type = blockIdx.y, chunk = blockIdx.x;
    int tid = threadIdx.x, lane = tid & 31, wid = tid >> 5;
    int idx = chunk * 1024 + tid;
    int v = (idx < NN) ? g_cnt[type * NN + idx] : 0;
    int inc = v;
#pragma unroll
    for (int o = 1; o < 32; o <<= 1) {
        int y = __shfl_up_sync(0xffffffffu, inc, o);
        if (lane >= o) inc += y;
    }
    if (lane == 31) warpsums[wid] = inc;
    __syncthreads();
    if (tid < 32) {
        int w = warpsums[tid];
        int s = w;
#pragma unroll
        for (int o = 1; o < 32; o <<= 1) {
            int y = __shfl_up_sync(0xffffffffu, s, o);
            if (tid >= o) s += y;
        }
        warpsums[tid] = s - w;
    }
    __syncthreads();
    int excl = inc - v + warpsums[wid];
    if (idx < NN) g_off[type * NN + idx] = excl;
    if (tid == 1023) g_bsum[type * 64 + chunk] = excl + v;
}

__global__ void scan2_kernel() {
    int type = threadIdx.x;
    if (type < 2) {
        int run = 0;
        for (int c = 0; c < NCHUNK; c++) {
            int v = g_bsum[type * 64 + c];
            g_bsum[type * 64 + c] = run;
            run += v;
        }
    }
}

__global__ __launch_bounds__(1024) void scan3_kernel() {
    int type = blockIdx.y, chunk = blockIdx.x;
    int idx = chunk * 1024 + threadIdx.x;
    if (idx < NN) {
        int o = g_off[type * NN + idx] + g_bsum[type * 64 + chunk];
        g_off[type * NN + idx] = o;
        g_cur[type * NN + idx] = o;
    }
}

// ---------------------------------------------------------------
// boundary MLP: b[t][n] = sigmoid(MLP(x[t][n]))   128->64->32->1
// ---------------------------------------------------------------
__global__ __launch_bounds__(128) void boundary_kernel(
    const float* __restrict__ x,
    const float* __restrict__ bdW1, const float* __restrict__ bdb1,
    const float* __restrict__ bdW2, const float* __restrict__ bdb2,
    const float* __restrict__ bdW3, const float* __restrict__ bdb3)
{
    __shared__ float W1s[128 * 64];
    __shared__ float W2s[64 * 32];
    __shared__ float W3s[32];
    __shared__ float b1s[64], b2s[32];
    __shared__ float b3s;

    int type = blockIdx.y;
    int tid = threadIdx.x;
    const float* W1 = bdW1 + (size_t)type * 128 * 64;
    const float* W2 = bdW2 + (size_t)type * 64 * 32;
    for (int i = tid; i < 128 * 64; i += 128) W1s[i] = W1[i];
    for (int i = tid; i < 64 * 32; i += 128) W2s[i] = W2[i];
    if (tid < 32) W3s[tid] = bdW3[type * 32 + tid];
    if (tid < 64) b1s[tid] = bdb1[type * 64 + tid];
    if (tid < 32) b2s[tid] = bdb2[type * 32 + tid];
    if (tid == 0) b3s = bdb3[type];
    __syncthreads();

    int node = blockIdx.x * 128 + tid;
    if (node >= NN) return;

    const float4* xr = (const float4*)(x + ((size_t)type * NN + node) * DD);

    float h1[64];
#pragma unroll
    for (int j = 0; j < 64; j++) h1[j] = b1s[j];

    for (int d4 = 0; d4 < 32; d4++) {
        float4 xv = xr[d4];
        float vs[4] = {xv.x, xv.y, xv.z, xv.w};
#pragma unroll
        for (int dd = 0; dd < 4; dd++) {
            float v = vs[dd];
            const float4* wr = (const float4*)&W1s[(d4 * 4 + dd) * 64];
#pragma unroll
            for (int q = 0; q < 16; q++) {
                float4 w = wr[q];
                h1[q * 4 + 0] += v * w.x;
                h1[q * 4 + 1] += v * w.y;
                h1[q * 4 + 2] += v * w.z;
                h1[q * 4 + 3] += v * w.w;
            }
        }
    }
#pragma unroll
    for (int j = 0; j < 64; j++) h1[j] = fmaxf(h1[j], 0.f);

    float h2[32];
#pragma unroll
    for (int j = 0; j < 32; j++) h2[j] = b2s[j];
#pragma unroll
    for (int k = 0; k < 64; k++) {
        float v = h1[k];
        const float4* wr = (const float4*)&W2s[k * 32];
#pragma unroll
        for (int q = 0; q < 8; q++) {
            float4 w = wr[q];
            h2[q * 4 + 0] += v * w.x;
            h2[q * 4 + 1] += v * w.y;
            h2[q * 4 + 2] += v * w.z;
            h2[q * 4 + 3] += v * w.w;
        }
    }
    float z = b3s;
#pragma unroll
    for (int k = 0; k < 32; k++) z += fmaxf(h2[k], 0.f) * W3s[k];

    g_b[type * NN + node] = 1.f / (1.f + expf(-z));
}

// ---------------------------------------------------------------
// shared GEMM microkernel: C(64x128) += Xs(64x128) * Ws(128x128)
// ---------------------------------------------------------------
__device__ __forceinline__ void gemm_tile(const float* Xs, const float* Ws,
                                          float acc[4][8], int tx, int ty)
{
#pragma unroll 4
    for (int k = 0; k < 128; k++) {
        float a0 = Xs[(ty * 4 + 0) * XPITCH + k];
        float a1 = Xs[(ty * 4 + 1) * XPITCH + k];
        float a2 = Xs[(ty * 4 + 2) * XPITCH + k];
        float a3 = Xs[(ty * 4 + 3) * XPITCH + k];
        const float4* wp = (const float4*)&Ws[k * 128 + tx * 8];
        float4 w0 = wp[0], w1 = wp[1];
        float wv[8] = {w0.x, w0.y, w0.z, w0.w, w1.x, w1.y, w1.z, w1.w};
#pragma unroll
        for (int j = 0; j < 8; j++) {
            acc[0][j] += a0 * wv[j];
            acc[1][j] += a1 * wv[j];
            acc[2][j] += a2 * wv[j];
            acc[3][j] += a3 * wv[j];
        }
    }
}

// ---------------------------------------------------------------
// edge-type transform: t = relu(x @ W1 + b1) @ W2 + b2  (fp16 output)
// ---------------------------------------------------------------
__global__ __launch_bounds__(256, 2) void et_kernel(
    const float* __restrict__ x,
    const float* __restrict__ W1g, const float* __restrict__ b1g,
    const float* __restrict__ W2g, const float* __restrict__ b2g)
{
    extern __shared__ float sm[];
    float* Xs = sm;
    float* Ws = sm + TM * XPITCH;

    int type = blockIdx.y;
    int m0 = blockIdx.x * TM;
    int tid = threadIdx.x;
    int tx = tid & 15, ty = tid >> 4;
    const float* xb = x + (size_t)type * NN * DD;

    for (int i = tid; i < TM * 32; i += 256) {
        int r = i >> 5, c4 = i & 31;
        int row = m0 + r;
        float4 v = (row < NN) ? ((const float4*)(xb + (size_t)row * DD))[c4]
                              : make_float4(0.f, 0.f, 0.f, 0.f);
        float* dst = &Xs[r * XPITCH + c4 * 4];
        dst[0] = v.x; dst[1] = v.y; dst[2] = v.z; dst[3] = v.w;
    }
    {
        const float4* W1 = (const float4*)(W1g + (size_t)type * 128 * 128);
        for (int i = tid; i < 128 * 32; i += 256) ((float4*)Ws)[i] = W1[i];
    }
    __syncthreads();

    float acc[4][8];
    {
        const float* b1 = b1g + type * 128 + tx * 8;
#pragma unroll
        for (int j = 0; j < 8; j++) {
            float bv = b1[j];
            acc[0][j] = bv; acc[1][j] = bv; acc[2][j] = bv; acc[3][j] = bv;
        }
    }
    gemm_tile(Xs, Ws, acc, tx, ty);
    __syncthreads();

#pragma unroll
    for (int i = 0; i < 4; i++)
#pragma unroll
        for (int j = 0; j < 8; j++)
            Xs[(ty * 4 + i) * XPITCH + tx * 8 + j] = fmaxf(acc[i][j], 0.f);
    {
        const float4* W2 = (const float4*)(W2g + (size_t)type * 128 * 128);
        for (int i = tid; i < 128 * 32; i += 256) ((float4*)Ws)[i] = W2[i];
    }
    __syncthreads();

    {
        const float* b2 = b2g + type * 128 + tx * 8;
#pragma unroll
        for (int j = 0; j < 8; j++) {
            float bv = b2[j];
            acc[0][j] = bv; acc[1][j] = bv; acc[2][j] = bv; acc[3][j] = bv;
        }
    }
    gemm_tile(Xs, Ws, acc, tx, ty);

    // store as fp16: 8 halves (16B) per thread per row
    uint4* tb = (uint4*)(g_t + (size_t)type * NN * DD);
#pragma unroll
    for (int i = 0; i < 4; i++) {
        int row = m0 + ty * 4 + i;
        if (row < NN) {
            __half2 p0 = __floats2half2_rn(acc[i][0], acc[i][1]);
            __half2 p1 = __floats2half2_rn(acc[i][2], acc[i][3]);
            __half2 p2 = __floats2half2_rn(acc[i][4], acc[i][5]);
            __half2 p3 = __floats2half2_rn(acc[i][6], acc[i][7]);
            uint4 u;
            u.x = *(unsigned*)&p0; u.y = *(unsigned*)&p1;
            u.z = *(unsigned*)&p2; u.w = *(unsigned*)&p3;
            tb[(size_t)row * 16 + tx] = u;
        }
    }
}

// ---------------------------------------------------------------
// per-edge coefficient MLP + CSR binning (fused)
// ---------------------------------------------------------------
__global__ __launch_bounds__(256) void coef_order_kernel(
    const int* __restrict__ ei, const float* __restrict__ ea,
    const float* __restrict__ bwW1, const float* __restrict__ bwb1,
    const float* __restrict__ bwW2, const float* __restrict__ bwb2,
    const float* __restrict__ bwW3, const float* __restrict__ bwb3)
{
    __shared__ float W1s[64], B1s[32], W2s[512], B2s[16], W3s[16];
    __shared__ float B3s;
    int type = blockIdx.y;
    int tid = threadIdx.x;
    if (tid < 64) W1s[tid] = bwW1[type * 64 + tid];
    if (tid < 32) B1s[tid] = bwb1[type * 32 + tid];
    for (int i = tid; i < 512; i += 256) W2s[i] = bwW2[type * 512 + i];
    if (tid < 16) B2s[tid] = bwb2[type * 16 + tid];
    if (tid < 16) W3s[tid] = bwW3[type * 16 + tid];
    if (tid == 0) B3s = bwb3[type];
    __syncthreads();

    int j = blockIdx.x * 256 + tid;
    if (j >= EE) return;
    const int* eib = ei + (size_t)type * 2 * EE;
    int s = eib[j];
    int d = eib[EE + j];
    float sb = g_b[type * NN + s];
    float db = g_b[(1 - type) * NN + d];

    float h1[32];
#pragma unroll
    for (int q = 0; q < 32; q++)
        h1[q] = fmaxf(sb * W1s[q] + db * W1s[32 + q] + B1s[q], 0.f);

    float4 h2v[4];
#pragma unroll
    for (int p = 0; p < 4; p++) h2v[p] = ((const float4*)B2s)[p];
    const float4* W2v = (const float4*)W2s;
#pragma unroll
    for (int q = 0; q < 32; q++) {
        float v = h1[q];
#pragma unroll
        for (int p = 0; p < 4; p++) {
            float4 w = W2v[q * 4 + p];
            h2v[p].x += v * w.x;
            h2v[p].y += v * w.y;
            h2v[p].z += v * w.z;
            h2v[p].w += v * w.w;
        }
    }
    float z = B3s;
#pragma unroll
    for (int p = 0; p < 4; p++) {
        z += fmaxf(h2v[p].x, 0.f) * W3s[p * 4 + 0];
        z += fmaxf(h2v[p].y, 0.f) * W3s[p * 4 + 1];
        z += fmaxf(h2v[p].z, 0.f) * W3s[p * 4 + 2];
        z += fmaxf(h2v[p].w, 0.f) * W3s[p * 4 + 3];
    }

    float w = 1.f / (1.f + expf(-z));
    if (sb > 0.3f || db > 0.3f) w *= 2.f;
    float c = ea[(size_t)type * EE + j] * w;

    int pos = atomicAdd(&g_cur[type * NN + d], 1);
    g_srcA[(size_t)type * EE + pos] = s;
    g_cvalA[(size_t)type * EE + pos] = c;
}

// ---------------------------------------------------------------
// gather: upd[to][n] = x[to][n] + sum over CSR(type e=1-to, dst n)
// warp per destination node; rows are fp16 (256B), lane owns 4 halves
// ---------------------------------------------------------------
__global__ __launch_bounds__(256) void gather_kernel(const float* __restrict__ x)
{
    int to = blockIdx.y;
    int e = 1 - to;
    int lane = threadIdx.x & 31;
    int warp = threadIdx.x >> 5;
    int n = blockIdx.x * 8 + warp;
    if (n >= NN) return;

    int base = e * NN + n;
    int st = g_off[base];
    int en = g_cur[base];

    const uint2* tb = (const uint2*)(g_t + (size_t)e * NN * DD);
    const int* srcp = g_srcA + (size_t)e * EE;
    const float* cvp = g_cvalA + (size_t)e * EE;

    float4 acc = ((const float4*)(x + ((size_t)to * NN + n) * DD))[lane];

    int i = st;
    for (; i + 3 < en; i += 4) {
        int s0 = __ldg(srcp + i),     s1 = __ldg(srcp + i + 1);
        int s2 = __ldg(srcp + i + 2), s3 = __ldg(srcp + i + 3);
        float c0 = __ldg(cvp + i),     c1 = __ldg(cvp + i + 1);
        float c2 = __ldg(cvp + i + 2), c3 = __ldg(cvp + i + 3);
        uint2 h0 = tb[(size_t)s0 * 32 + lane];
        uint2 h1 = tb[(size_t)s1 * 32 + lane];
        uint2 h2 = tb[(size_t)s2 * 32 + lane];
        uint2 h3 = tb[(size_t)s3 * 32 + lane];
        float2 a0 = __half22float2(*(__half2*)&h0.x), b0 = __half22float2(*(__half2*)&h0.y);
        float2 a1 = __half22float2(*(__half2*)&h1.x), b1 = __half22float2(*(__half2*)&h1.y);
        float2 a2 = __half22float2(*(__half2*)&h2.x), b2 = __half22float2(*(__half2*)&h2.y);
        float2 a3 = __half22float2(*(__half2*)&h3.x), b3 = __half22float2(*(__half2*)&h3.y);
        acc.x += a0.x * c0; acc.y += a0.y * c0; acc.z += b0.x * c0; acc.w += b0.y * c0;
        acc.x += a1.x * c1; acc.y += a1.y * c1; acc.z += b1.x * c1; acc.w += b1.y * c1;
        acc.x += a2.x * c2; acc.y += a2.y * c2; acc.z += b2.x * c2; acc.w += b2.y * c2;
        acc.x += a3.x * c3; acc.y += a3.y * c3; acc.z += b3.x * c3; acc.w += b3.y * c3;
    }
    for (; i < en; i++) {
        int s0 = __ldg(srcp + i);
        float c0 = __ldg(cvp + i);
        uint2 h0 = tb[(size_t)s0 * 32 + lane];
        float2 a0 = __half22float2(*(__half2*)&h0.x), b0 = __half22float2(*(__half2*)&h0.y);
        acc.x += a0.x * c0; acc.y += a0.y * c0; acc.z += b0.x * c0; acc.w += b0.y * c0;
    }

    ((float4*)(g_upd + ((size_t)to * NN + n) * DD))[lane] = acc;
}

// ---------------------------------------------------------------
// node update: out = relu(LN(upd @ nuW + nub) * g + b)
// ---------------------------------------------------------------
__global__ __launch_bounds__(256, 2) void nu_kernel(
    const float* __restrict__ nuW, const float* __restrict__ nub,
    const float* __restrict__ lng, const float* __restrict__ lnb,
    float* __restrict__ out)
{
    extern __shared__ float sm[];
    float* Us = sm;
    float* Ws = sm + TM * XPITCH;
    float* muS = Ws + 128 * 128;
    float* rsS = muS + 64;

    int type = blockIdx.y;
    int m0 = blockIdx.x * TM;
    int tid = threadIdx.x;
    int tx = tid & 15, ty = tid >> 4;
    const float* ub = g_upd + (size_t)type * NN * DD;

    for (int i = tid; i < TM * 32; i += 256) {
        int r = i >> 5, c4 = i & 31;
        int row = m0 + r;
        float4 v = (row < NN) ? ((const float4*)(ub + (size_t)row * DD))[c4]
                              : make_float4(0.f, 0.f, 0.f, 0.f);
        float* dst = &Us[r * XPITCH + c4 * 4];
        dst[0] = v.x; dst[1] = v.y; dst[2] = v.z; dst[3] = v.w;
    }
    {
        const float4* W = (const float4*)(nuW + (size_t)type * 128 * 128);
        for (int i = tid; i < 128 * 32; i += 256) ((float4*)Ws)[i] = W[i];
    }
    __syncthreads();

    float acc[4][8];
    {
        const float* bb = nub + type * 128 + tx * 8;
#pragma unroll
        for (int j = 0; j < 8; j++) {
            float bv = bb[j];
            acc[0][j] = bv; acc[1][j] = bv; acc[2][j] = bv; acc[3][j] = bv;
        }
    }
    gemm_tile(Us, Ws, acc, tx, ty);
    __syncthreads();

#pragma unroll
    for (int i = 0; i < 4; i++)
#pragma unroll
        for (int j = 0; j < 8; j++)
            Us[(ty * 4 + i) * XPITCH + tx * 8 + j] = acc[i][j];
    __syncthreads();

    if (tid < 64) {
        const float* zr = &Us[tid * XPITCH];
        float s = 0.f;
        for (int c = 0; c < 128; c++) s += zr[c];
        float mu = s * (1.f / 128.f);
        float v = 0.f;
        for (int c = 0; c < 128; c++) { float dlt = zr[c] - mu; v += dlt * dlt; }
        v *= (1.f / 128.f);
        muS[tid] = mu;
        rsS[tid] = rsqrtf(v + 1e-5f);
    }
    __syncthreads();

    const float* g = lng + type * 128;
    const float* be = lnb + type * 128;
    float* ob = out + (size_t)type * NN * DD;
#pragma unroll
    for (int i = 0; i < 4; i++) {
        int r = ty * 4 + i;
        int row = m0 + r;
        if (row < NN) {
            float mu = muS[r], rv = rsS[r];
            float o[8];
#pragma unroll
            for (int j = 0; j < 8; j++) {
                int col = tx * 8 + j;
                float z = Us[r * XPITCH + col];
                o[j] = fmaxf((z - mu) * rv * g[col] + be[col], 0.f);
            }
            float4* op = (float4*)(ob + (size_t)row * DD + tx * 8);
            op[0] = make_float4(o[0], o[1], o[2], o[3]);
            op[1] = make_float4(o[4], o[5], o[6], o[7]);
        }
    }
}

// ---------------------------------------------------------------
extern "C" void kernel_launch(void* const* d_in, const int* in_sizes, int n_in,
                              void* d_out, int out_size)
{
    const float* x    = (const float*)d_in[0];
    const int*   ei   = (const int*)d_in[1];
    const float* ea   = (const float*)d_in[2];
    const float* bdW1 = (const float*)d_in[3];
    const float* bdb1 = (const float*)d_in[4];
    const float* bdW2 = (const float*)d_in[5];
    const float* bdb2 = (const float*)d_in[6];
    const float* bdW3 = (const float*)d_in[7];
    const float* bdb3 = (const float*)d_in[8];
    const float* etW1 = (const float*)d_in[9];
    const float* etb1 = (const float*)d_in[10];
    const float* etW2 = (const float*)d_in[11];
    const float* etb2 = (const float*)d_in[12];
    const float* bwW1 = (const float*)d_in[13];
    const float* bwb1 = (const float*)d_in[14];
    const float* bwW2 = (const float*)d_in[15];
    const float* bwb2 = (const float*)d_in[16];
    const float* bwW3 = (const float*)d_in[17];
    const float* bwb3 = (const float*)d_in[18];
    const float* nuW  = (const float*)d_in[19];
    const float* nub  = (const float*)d_in[20];
    const float* lng  = (const float*)d_in[21];
    const float* lnb  = (const float*)d_in[22];
    float* out = (float*)d_out;

    const int SMEM_ET = (TM * XPITCH + 128 * 128) * 4;
    const int SMEM_NU = (TM * XPITCH + 128 * 128 + 128) * 4;
    cudaFuncSetAttribute((const void*)et_kernel,
                         cudaFuncAttributeMaxDynamicSharedMemorySize, SMEM_ET);
    cudaFuncSetAttribute((const void*)nu_kernel,
                         cudaFuncAttributeMaxDynamicSharedMemorySize, SMEM_NU);

    prep_kernel<<<(2 * NN + 255) / 256, 256>>>();
    hist_kernel<<<dim3((EE + 255) / 256, 2), 256>>>(ei);
    boundary_kernel<<<dim3((NN + 127) / 128, 2), 128>>>(x, bdW1, bdb1, bdW2, bdb2, bdW3, bdb3);
    scan1_kernel<<<dim3(NCHUNK, 2), 1024>>>();
    scan2_kernel<<<1, 32>>>();
    scan3_kernel<<<dim3(NCHUNK, 2), 1024>>>();
    et_kernel<<<dim3((NN + TM - 1) / TM, 2), 256, SMEM_ET>>>(x, etW1, etb1, etW2, etb2);
    coef_order_kernel<<<dim3((EE + 255) / 256, 2), 256>>>(ei, ea, bwW1, bwb1, bwW2, bwb2, bwW3, bwb3);
    gather_kernel<<<dim3((NN + 7) / 8, 2), 256>>>(x);
    nu_kernel<<<dim3((NN + TM - 1) / TM, 2), 256, SMEM_NU>>>(nuW, nub, lng, lnb, out);
}

// round 5
// speedup vs baseline: 2.1726x; 1.3709x over previous
#include <cuda_runtime.h>
#include <cuda_fp16.h>
#include <cuda_bf16.h>
#include <mma.h>
#include <math.h>

using namespace nvcuda;

#define NN 50000
#define DD 128
#define EE 800000
#define NCHUNK 49   // ceil(50000/1024)

#define APITCH 136  // half pitch for A/B smem tiles
#define CPITCH 132  // float pitch for C smem tile
#define GT 128      // gemm output tile (M and N)
#define NTILE 391   // ceil(50000/128)

// -------- device scratch (no runtime allocation allowed) --------
__device__ float  g_b[2 * NN];               // boundary scores
__device__ __half g_t[2 * (size_t)NN * DD];  // transformed features (fp16)
__device__ float  g_upd[2 * (size_t)NN * DD];// x + aggregated messages
__device__ int    g_cnt[2 * NN];
__device__ int    g_off[2 * NN];
__device__ int    g_cur[2 * NN];
__device__ int    g_bsum[2 * 64];
__device__ int    g_srcA[2 * (size_t)EE];
__device__ float  g_cvalA[2 * (size_t)EE];

// ---------------------------------------------------------------
__global__ void prep_kernel() {
    int i = blockIdx.x * blockDim.x + threadIdx.x;
    if (i < 2 * NN) g_cnt[i] = 0;
}

__global__ __launch_bounds__(256) void hist_kernel(const int* __restrict__ ei) {
    int type = blockIdx.y;
    int j = blockIdx.x * 256 + threadIdx.x;
    if (j >= EE) return;
    int d = ei[(size_t)type * 2 * EE + EE + j];
    atomicAdd(&g_cnt[type * NN + d], 1);
}

// ---------------------------------------------------------------
// decoupled 3-phase exclusive scan
// ---------------------------------------------------------------
__global__ __launch_bounds__(1024) void scan1_kernel() {
    __shared__ int warpsums[32];
    int type = blockIdx.y, chunk = blockIdx.x;
    int tid = threadIdx.x, lane = tid & 31, wid = tid >> 5;
    int idx = chunk * 1024 + tid;
    int v = (idx < NN) ? g_cnt[type * NN + idx] : 0;
    int inc = v;
#pragma unroll
    for (int o = 1; o < 32; o <<= 1) {
        int y = __shfl_up_sync(0xffffffffu, inc, o);
        if (lane >= o) inc += y;
    }
    if (lane == 31) warpsums[wid] = inc;
    __syncthreads();
    if (tid < 32) {
        int w = warpsums[tid];
        int s = w;
#pragma unroll
        for (int o = 1; o < 32; o <<= 1) {
            int y = __shfl_up_sync(0xffffffffu, s, o);
            if (tid >= o) s += y;
        }
        warpsums[tid] = s - w;
    }
    __syncthreads();
    int excl = inc - v + warpsums[wid];
    if (idx < NN) g_off[type * NN + idx] = excl;
    if (tid == 1023) g_bsum[type * 64 + chunk] = excl + v;
}

__global__ void scan2_kernel() {
    int type = threadIdx.x;
    if (type < 2) {
        int run = 0;
        for (int c = 0; c < NCHUNK; c++) {
            int v = g_bsum[type * 64 + c];
            g_bsum[type * 64 + c] = run;
            run += v;
        }
    }
}

__global__ __launch_bounds__(1024) void scan3_kernel() {
    int type = blockIdx.y, chunk = blockIdx.x;
    int idx = chunk * 1024 + threadIdx.x;
    if (idx < NN) {
        int o = g_off[type * NN + idx] + g_bsum[type * 64 + chunk];
        g_off[type * NN + idx] = o;
        g_cur[type * NN + idx] = o;
    }
}

// ---------------------------------------------------------------
// boundary MLP: b[t][n] = sigmoid(MLP(x[t][n]))   128->64->32->1
// ---------------------------------------------------------------
__global__ __launch_bounds__(128) void boundary_kernel(
    const float* __restrict__ x,
    const float* __restrict__ bdW1, const float* __restrict__ bdb1,
    const float* __restrict__ bdW2, const float* __restrict__ bdb2,
    const float* __restrict__ bdW3, const float* __restrict__ bdb3)
{
    __shared__ float W1s[128 * 64];
    __shared__ float W2s[64 * 32];
    __shared__ float W3s[32];
    __shared__ float b1s[64], b2s[32];
    __shared__ float b3s;

    int type = blockIdx.y;
    int tid = threadIdx.x;
    const float* W1 = bdW1 + (size_t)type * 128 * 64;
    const float* W2 = bdW2 + (size_t)type * 64 * 32;
    for (int i = tid; i < 128 * 64; i += 128) W1s[i] = W1[i];
    for (int i = tid; i < 64 * 32; i += 128) W2s[i] = W2[i];
    if (tid < 32) W3s[tid] = bdW3[type * 32 + tid];
    if (tid < 64) b1s[tid] = bdb1[type * 64 + tid];
    if (tid < 32) b2s[tid] = bdb2[type * 32 + tid];
    if (tid == 0) b3s = bdb3[type];
    __syncthreads();

    int node = blockIdx.x * 128 + tid;
    if (node >= NN) return;

    const float4* xr = (const float4*)(x + ((size_t)type * NN + node) * DD);

    float h1[64];
#pragma unroll
    for (int j = 0; j < 64; j++) h1[j] = b1s[j];

    for (int d4 = 0; d4 < 32; d4++) {
        float4 xv = xr[d4];
        float vs[4] = {xv.x, xv.y, xv.z, xv.w};
#pragma unroll
        for (int dd = 0; dd < 4; dd++) {
            float v = vs[dd];
            const float4* wr = (const float4*)&W1s[(d4 * 4 + dd) * 64];
#pragma unroll
            for (int q = 0; q < 16; q++) {
                float4 w = wr[q];
                h1[q * 4 + 0] += v * w.x;
                h1[q * 4 + 1] += v * w.y;
                h1[q * 4 + 2] += v * w.z;
                h1[q * 4 + 3] += v * w.w;
            }
        }
    }
#pragma unroll
    for (int j = 0; j < 64; j++) h1[j] = fmaxf(h1[j], 0.f);

    float h2[32];
#pragma unroll
    for (int j = 0; j < 32; j++) h2[j] = b2s[j];
#pragma unroll
    for (int k = 0; k < 64; k++) {
        float v = h1[k];
        const float4* wr = (const float4*)&W2s[k * 32];
#pragma unroll
        for (int q = 0; q < 8; q++) {
            float4 w = wr[q];
            h2[q * 4 + 0] += v * w.x;
            h2[q * 4 + 1] += v * w.y;
            h2[q * 4 + 2] += v * w.z;
            h2[q * 4 + 3] += v * w.w;
        }
    }
    float z = b3s;
#pragma unroll
    for (int k = 0; k < 32; k++) z += fmaxf(h2[k], 0.f) * W3s[k];

    g_b[type * NN + node] = 1.f / (1.f + expf(-z));
}

// ---------------------------------------------------------------
// helper: load a 128x128 f32 matrix (row-major, row stride 128) into
// fp16 smem tile with pitch APITCH. rows beyond limit are zeroed.
// ---------------------------------------------------------------
__device__ __forceinline__ void load_f32_to_h16(
    __half* dst, const float* src, int row0, int rowlim, int tid)
{
    for (int idx = tid; idx < 128 * 32; idx += 256) {
        int r = idx >> 5, c4 = idx & 31;
        int row = row0 + r;
        float4 v = (row < rowlim) ? ((const float4*)(src + (size_t)row * DD))[c4]
                                  : make_float4(0.f, 0.f, 0.f, 0.f);
        __half2* d = (__half2*)&dst[r * APITCH + c4 * 4];
        d[0] = __floats2half2_rn(v.x, v.y);
        d[1] = __floats2half2_rn(v.z, v.w);
    }
}

__device__ __forceinline__ void load_w_to_h16(
    __half* dst, const float* w, int tid)
{
    for (int idx = tid; idx < 128 * 32; idx += 256) {
        int r = idx >> 5, c4 = idx & 31;
        float4 v = ((const float4*)(w + (size_t)r * DD))[c4];
        __half2* d = (__half2*)&dst[r * APITCH + c4 * 4];
        d[0] = __floats2half2_rn(v.x, v.y);
        d[1] = __floats2half2_rn(v.z, v.w);
    }
}

// wmma gemm over the tile: C(128x128) = A(128x128) @ B(128x128)
// warps: wm = wid&3 (32 rows each), wn = wid>>2 (64 cols each)
__device__ __forceinline__ void wmma_tile(
    const __half* Ah, const __half* Bh, float* Cs, int wid)
{
    int wm = wid & 3, wn = wid >> 2;
    wmma::fragment<wmma::accumulator, 16, 16, 16, float> acc[2][4];
#pragma unroll
    for (int i = 0; i < 2; i++)
#pragma unroll
        for (int j = 0; j < 4; j++) wmma::fill_fragment(acc[i][j], 0.f);

#pragma unroll
    for (int k = 0; k < 8; k++) {
        wmma::fragment<wmma::matrix_a, 16, 16, 16, __half, wmma::row_major> a[2];
        wmma::fragment<wmma::matrix_b, 16, 16, 16, __half, wmma::row_major> b[4];
#pragma unroll
        for (int i = 0; i < 2; i++)
            wmma::load_matrix_sync(a[i], Ah + (wm * 32 + i * 16) * APITCH + k * 16, APITCH);
#pragma unroll
        for (int j = 0; j < 4; j++)
            wmma::load_matrix_sync(b[j], Bh + (k * 16) * APITCH + wn * 64 + j * 16, APITCH);
#pragma unroll
        for (int i = 0; i < 2; i++)
#pragma unroll
            for (int j = 0; j < 4; j++)
                wmma::mma_sync(acc[i][j], a[i], b[j], acc[i][j]);
    }
#pragma unroll
    for (int i = 0; i < 2; i++)
#pragma unroll
        for (int j = 0; j < 4; j++)
            wmma::store_matrix_sync(Cs + (wm * 32 + i * 16) * CPITCH + wn * 64 + j * 16,
                                    acc[i][j], CPITCH, wmma::mem_row_major);
}

// ---------------------------------------------------------------
// et (tensor core): t = relu(x @ W1 + b1) @ W2 + b2  -> g_t (fp16)
// ---------------------------------------------------------------
__global__ __launch_bounds__(256, 1) void et_wmma_kernel(
    const float* __restrict__ x,
    const float* __restrict__ W1g, const float* __restrict__ b1g,
    const float* __restrict__ W2g, const float* __restrict__ b2g)
{
    extern __shared__ char smem_raw[];
    __half* Ah = (__half*)smem_raw;                  // 128*APITCH halves
    __half* Bh = Ah + 128 * APITCH;                  // 128*APITCH halves
    float*  Cs = (float*)(Bh + 128 * APITCH);        // 128*CPITCH floats

    int type = blockIdx.y;
    int m0 = blockIdx.x * GT;
    int tid = threadIdx.x;
    int wid = tid >> 5;

    load_f32_to_h16(Ah, x + (size_t)type * NN * DD, m0, NN, tid);
    load_w_to_h16(Bh, W1g + (size_t)type * 128 * 128, tid);
    __syncthreads();

    wmma_tile(Ah, Bh, Cs, wid);
    __syncthreads();

    // relu + bias -> Ah (fp16), reload W2
    const float* b1 = b1g + type * 128;
    for (int idx = tid; idx < 128 * 64; idx += 256) {
        int r = idx >> 6, c2 = (idx & 63) * 2;
        float z0 = Cs[r * CPITCH + c2]     + b1[c2];
        float z1 = Cs[r * CPITCH + c2 + 1] + b1[c2 + 1];
        *(__half2*)&Ah[r * APITCH + c2] = __floats2half2_rn(fmaxf(z0, 0.f), fmaxf(z1, 0.f));
    }
    load_w_to_h16(Bh, W2g + (size_t)type * 128 * 128, tid);
    __syncthreads();

    wmma_tile(Ah, Bh, Cs, wid);
    __syncthreads();

    const float* b2 = b2g + type * 128;
    __half2* tb = (__half2*)(g_t + (size_t)type * NN * DD);
    for (int idx = tid; idx < 128 * 64; idx += 256) {
        int r = idx >> 6, c2idx = idx & 63;
        int row = m0 + r;
        if (row < NN) {
            int c2 = c2idx * 2;
            float z0 = Cs[r * CPITCH + c2]     + b2[c2];
            float z1 = Cs[r * CPITCH + c2 + 1] + b2[c2 + 1];
            tb[(size_t)row * 64 + c2idx] = __floats2half2_rn(z0, z1);
        }
    }
}

// ---------------------------------------------------------------
// per-edge coefficient MLP + CSR binning (fused)
// ---------------------------------------------------------------
__global__ __launch_bounds__(256) void coef_order_kernel(
    const int* __restrict__ ei, const float* __restrict__ ea,
    const float* __restrict__ bwW1, const float* __restrict__ bwb1,
    const float* __restrict__ bwW2, const float* __restrict__ bwb2,
    const float* __restrict__ bwW3, const float* __restrict__ bwb3)
{
    __shared__ float W1s[64], B1s[32], W2s[512], B2s[16], W3s[16];
    __shared__ float B3s;
    int type = blockIdx.y;
    int tid = threadIdx.x;
    if (tid < 64) W1s[tid] = bwW1[type * 64 + tid];
    if (tid < 32) B1s[tid] = bwb1[type * 32 + tid];
    for (int i = tid; i < 512; i += 256) W2s[i] = bwW2[type * 512 + i];
    if (tid < 16) B2s[tid] = bwb2[type * 16 + tid];
    if (tid < 16) W3s[tid] = bwW3[type * 16 + tid];
    if (tid == 0) B3s = bwb3[type];
    __syncthreads();

    int j = blockIdx.x * 256 + tid;
    if (j >= EE) return;
    const int* eib = ei + (size_t)type * 2 * EE;
    int s = eib[j];
    int d = eib[EE + j];
    float sb = g_b[type * NN + s];
    float db = g_b[(1 - type) * NN + d];

    float h1[32];
#pragma unroll
    for (int q = 0; q < 32; q++)
        h1[q] = fmaxf(sb * W1s[q] + db * W1s[32 + q] + B1s[q], 0.f);

    float4 h2v[4];
#pragma unroll
    for (int p = 0; p < 4; p++) h2v[p] = ((const float4*)B2s)[p];
    const float4* W2v = (const float4*)W2s;
#pragma unroll
    for (int q = 0; q < 32; q++) {
        float v = h1[q];
#pragma unroll
        for (int p = 0; p < 4; p++) {
            float4 w = W2v[q * 4 + p];
            h2v[p].x += v * w.x;
            h2v[p].y += v * w.y;
            h2v[p].z += v * w.z;
            h2v[p].w += v * w.w;
        }
    }
    float z = B3s;
#pragma unroll
    for (int p = 0; p < 4; p++) {
        z += fmaxf(h2v[p].x, 0.f) * W3s[p * 4 + 0];
        z += fmaxf(h2v[p].y, 0.f) * W3s[p * 4 + 1];
        z += fmaxf(h2v[p].z, 0.f) * W3s[p * 4 + 2];
        z += fmaxf(h2v[p].w, 0.f) * W3s[p * 4 + 3];
    }

    float w = 1.f / (1.f + expf(-z));
    if (sb > 0.3f || db > 0.3f) w *= 2.f;
    float c = ea[(size_t)type * EE + j] * w;

    int pos = atomicAdd(&g_cur[type * NN + d], 1);
    g_srcA[(size_t)type * EE + pos] = s;
    g_cvalA[(size_t)type * EE + pos] = c;
}

// ---------------------------------------------------------------
// gather: upd[to][n] = x[to][n] + sum over CSR(type e=1-to, dst n)
// ---------------------------------------------------------------
__global__ __launch_bounds__(256) void gather_kernel(const float* __restrict__ x)
{
    int to = blockIdx.y;
    int e = 1 - to;
    int lane = threadIdx.x & 31;
    int warp = threadIdx.x >> 5;
    int n = blockIdx.x * 8 + warp;
    if (n >= NN) return;

    int base = e * NN + n;
    int st = g_off[base];
    int en = g_cur[base];

    const uint2* tb = (const uint2*)(g_t + (size_t)e * NN * DD);
    const int* srcp = g_srcA + (size_t)e * EE;
    const float* cvp = g_cvalA + (size_t)e * EE;

    float4 acc = ((const float4*)(x + ((size_t)to * NN + n) * DD))[lane];

    int i = st;
    for (; i + 3 < en; i += 4) {
        int s0 = __ldg(srcp + i),     s1 = __ldg(srcp + i + 1);
        int s2 = __ldg(srcp + i + 2), s3 = __ldg(srcp + i + 3);
        float c0 = __ldg(cvp + i),     c1 = __ldg(cvp + i + 1);
        float c2 = __ldg(cvp + i + 2), c3 = __ldg(cvp + i + 3);
        uint2 h0 = tb[(size_t)s0 * 32 + lane];
        uint2 h1 = tb[(size_t)s1 * 32 + lane];
        uint2 h2 = tb[(size_t)s2 * 32 + lane];
        uint2 h3 = tb[(size_t)s3 * 32 + lane];
        float2 a0 = __half22float2(*(__half2*)&h0.x), b0 = __half22float2(*(__half2*)&h0.y);
        float2 a1 = __half22float2(*(__half2*)&h1.x), b1 = __half22float2(*(__half2*)&h1.y);
        float2 a2 = __half22float2(*(__half2*)&h2.x), b2 = __half22float2(*(__half2*)&h2.y);
        float2 a3 = __half22float2(*(__half2*)&h3.x), b3 = __half22float2(*(__half2*)&h3.y);
        acc.x += a0.x * c0; acc.y += a0.y * c0; acc.z += b0.x * c0; acc.w += b0.y * c0;
        acc.x += a1.x * c1; acc.y += a1.y * c1; acc.z += b1.x * c1; acc.w += b1.y * c1;
        acc.x += a2.x * c2; acc.y += a2.y * c2; acc.z += b2.x * c2; acc.w += b2.y * c2;
        acc.x += a3.x * c3; acc.y += a3.y * c3; acc.z += b3.x * c3; acc.w += b3.y * c3;
    }
    for (; i < en; i++) {
        int s0 = __ldg(srcp + i);
        float c0 = __ldg(cvp + i);
        uint2 h0 = tb[(size_t)s0 * 32 + lane];
        float2 a0 = __half22float2(*(__half2*)&h0.x), b0 = __half22float2(*(__half2*)&h0.y);
        acc.x += a0.x * c0; acc.y += a0.y * c0; acc.z += b0.x * c0; acc.w += b0.y * c0;
    }

    ((float4*)(g_upd + ((size_t)to * NN + n) * DD))[lane] = acc;
}

// ---------------------------------------------------------------
// nu (tensor core): out = relu(LN(upd @ nuW + nub) * g + b)
// ---------------------------------------------------------------
__global__ __launch_bounds__(256, 1) void nu_wmma_kernel(
    const float* __restrict__ nuW, const float* __restrict__ nub,
    const float* __restrict__ lng, const float* __restrict__ lnb,
    float* __restrict__ out)
{
    extern __shared__ char smem_raw[];
    __half* Ah = (__half*)smem_raw;
    __half* Bh = Ah + 128 * APITCH;
    float*  Cs = (float*)(Bh + 128 * APITCH);
    float*  nubS = Cs + 128 * CPITCH;   // 128
    float*  gS   = nubS + 128;          // 128
    float*  lbS  = gS + 128;            // 128

    int type = blockIdx.y;
    int m0 = blockIdx.x * GT;
    int tid = threadIdx.x;
    int wid = tid >> 5;
    int lane = tid & 31;

    load_f32_to_h16(Ah, g_upd + (size_t)type * NN * DD, m0, NN, tid);
    load_w_to_h16(Bh, nuW + (size_t)type * 128 * 128, tid);
    if (tid < 128) {
        nubS[tid] = nub[type * 128 + tid];
        gS[tid]   = lng[type * 128 + tid];
        lbS[tid]  = lnb[type * 128 + tid];
    }
    __syncthreads();

    wmma_tile(Ah, Bh, Cs, wid);
    __syncthreads();

    // LN + relu epilogue: warp per 16 rows, lane owns 4 columns
    float* ob = out + (size_t)type * NN * DD;
    float4 bb = ((const float4*)nubS)[lane];
    float4 gg = ((const float4*)gS)[lane];
    float4 ll = ((const float4*)lbS)[lane];

    for (int rr = 0; rr < 16; rr++) {
        int r = wid * 16 + rr;
        int row = m0 + r;
        float4 c = ((const float4*)(Cs + r * CPITCH))[lane];
        c.x += bb.x; c.y += bb.y; c.z += bb.z; c.w += bb.w;
        float s = c.x + c.y + c.z + c.w;
#pragma unroll
        for (int o = 16; o > 0; o >>= 1) s += __shfl_xor_sync(0xffffffffu, s, o);
        float mu = s * (1.f / 128.f);
        float dx = c.x - mu, dy = c.y - mu, dz = c.z - mu, dw = c.w - mu;
        float v = dx * dx + dy * dy + dz * dz + dw * dw;
#pragma unroll
        for (int o = 16; o > 0; o >>= 1) v += __shfl_xor_sync(0xffffffffu, v, o);
        float rs = rsqrtf(v * (1.f / 128.f) + 1e-5f);
        if (row < NN) {
            float4 o4;
            o4.x = fmaxf(dx * rs * gg.x + ll.x, 0.f);
            o4.y = fmaxf(dy * rs * gg.y + ll.y, 0.f);
            o4.z = fmaxf(dz * rs * gg.z + ll.z, 0.f);
            o4.w = fmaxf(dw * rs * gg.w + ll.w, 0.f);
            ((float4*)(ob + (size_t)row * DD))[lane] = o4;
        }
    }
}

// ---------------------------------------------------------------
extern "C" void kernel_launch(void* const* d_in, const int* in_sizes, int n_in,
                              void* d_out, int out_size)
{
    const float* x    = (const float*)d_in[0];
    const int*   ei   = (const int*)d_in[1];
    const float* ea   = (const float*)d_in[2];
    const float* bdW1 = (const float*)d_in[3];
    const float* bdb1 = (const float*)d_in[4];
    const float* bdW2 = (const float*)d_in[5];
    const float* bdb2 = (const float*)d_in[6];
    const float* bdW3 = (const float*)d_in[7];
    const float* bdb3 = (const float*)d_in[8];
    const float* etW1 = (const float*)d_in[9];
    const float* etb1 = (const float*)d_in[10];
    const float* etW2 = (const float*)d_in[11];
    const float* etb2 = (const float*)d_in[12];
    const float* bwW1 = (const float*)d_in[13];
    const float* bwb1 = (const float*)d_in[14];
    const float* bwW2 = (const float*)d_in[15];
    const float* bwb2 = (const float*)d_in[16];
    const float* bwW3 = (const float*)d_in[17];
    const float* bwb3 = (const float*)d_in[18];
    const float* nuW  = (const float*)d_in[19];
    const float* nub  = (const float*)d_in[20];
    const float* lng  = (const float*)d_in[21];
    const float* lnb  = (const float*)d_in[22];
    float* out = (float*)d_out;

    // smem: A(h16) + B(h16) + C(f32) [+ 3*128 f32 for nu]
    const int SMEM_GEMM = 128 * APITCH * 2 * 2 + 128 * CPITCH * 4;      // 137216
    const int SMEM_NU   = SMEM_GEMM + 3 * 128 * 4;                      // +1536
    cudaFuncSetAttribute((const void*)et_wmma_kernel,
                         cudaFuncAttributeMaxDynamicSharedMemorySize, SMEM_GEMM);
    cudaFuncSetAttribute((const void*)nu_wmma_kernel,
                         cudaFuncAttributeMaxDynamicSharedMemorySize, SMEM_NU);

    prep_kernel<<<(2 * NN + 255) / 256, 256>>>();
    hist_kernel<<<dim3((EE + 255) / 256, 2), 256>>>(ei);
    scan1_kernel<<<dim3(NCHUNK, 2), 1024>>>();
    et_wmma_kernel<<<dim3(NTILE, 2), 256, SMEM_GEMM>>>(x, etW1, etb1, etW2, etb2);
    scan2_kernel<<<1, 32>>>();
    scan3_kernel<<<dim3(NCHUNK, 2), 1024>>>();
    boundary_kernel<<<dim3((NN + 127) / 128, 2), 128>>>(x, bdW1, bdb1, bdW2, bdb2, bdW3, bdb3);
    coef_order_kernel<<<dim3((EE + 255) / 256, 2), 256>>>(ei, ea, bwW1, bwb1, bwW2, bwb2, bwW3, bwb3);
    gather_kernel<<<dim3((NN + 7) / 8, 2), 256>>>(x);
    nu_wmma_kernel<<<dim3(NTILE, 2), 256, SMEM_NU>>>(nuW, nub, lng, lnb, out);
}

// round 7
// speedup vs baseline: 2.4640x; 1.1342x over previous
#include <cuda_runtime.h>
#include <cuda_fp16.h>
#include <cuda_bf16.h>
#include <mma.h>
#include <math.h>

using namespace nvcuda;

#define NN 50000
#define DD 128
#define EE 800000
#define NCHUNK 49   // ceil(50000/1024)

#define APITCH 136  // half pitch for A/B smem tiles
#define CPITCH 132  // float pitch for C smem tile
#define GTM 64      // gemm M tile (rows per CTA)
#define NTILE 782   // ceil(50000/64)

// -------- device scratch (no runtime allocation allowed) --------
__device__ float  g_b[2 * NN];               // boundary scores
__device__ __half g_t[2 * (size_t)NN * DD];  // transformed features (fp16)
__device__ float  g_upd[2 * (size_t)NN * DD];// x + aggregated messages
__device__ int    g_cnt[2 * NN];
__device__ int    g_off[2 * NN];
__device__ int    g_cur[2 * NN];
__device__ int    g_bsum[2 * 64];
__device__ int    g_srcA[2 * (size_t)EE];
__device__ float  g_cvalA[2 * (size_t)EE];

// ---------------------------------------------------------------
__global__ void prep_kernel() {
    int i = blockIdx.x * blockDim.x + threadIdx.x;
    if (i < 2 * NN) g_cnt[i] = 0;
}

__global__ __launch_bounds__(256) void hist_kernel(const int* __restrict__ ei) {
    int type = blockIdx.y;
    int j = blockIdx.x * 256 + threadIdx.x;
    if (j >= EE) return;
    int d = ei[(size_t)type * 2 * EE + EE + j];
    atomicAdd(&g_cnt[type * NN + d], 1);
}

// ---------------------------------------------------------------
// decoupled 3-phase exclusive scan
// ---------------------------------------------------------------
__global__ __launch_bounds__(1024) void scan1_kernel() {
    __shared__ int warpsums[32];
    int type = blockIdx.y, chunk = blockIdx.x;
    int tid = threadIdx.x, lane = tid & 31, wid = tid >> 5;
    int idx = chunk * 1024 + tid;
    int v = (idx < NN) ? g_cnt[type * NN + idx] : 0;
    int inc = v;
#pragma unroll
    for (int o = 1; o < 32; o <<= 1) {
        int y = __shfl_up_sync(0xffffffffu, inc, o);
        if (lane >= o) inc += y;
    }
    if (lane == 31) warpsums[wid] = inc;
    __syncthreads();
    if (tid < 32) {
        int w = warpsums[tid];
        int s = w;
#pragma unroll
        for (int o = 1; o < 32; o <<= 1) {
            int y = __shfl_up_sync(0xffffffffu, s, o);
            if (tid >= o) s += y;
        }
        warpsums[tid] = s - w;
    }
    __syncthreads();
    int excl = inc - v + warpsums[wid];
    if (idx < NN) g_off[type * NN + idx] = excl;
    if (tid == 1023) g_bsum[type * 64 + chunk] = excl + v;
}

__global__ void scan2_kernel() {
    int type = threadIdx.x;
    if (type < 2) {
        int run = 0;
        for (int c = 0; c < NCHUNK; c++) {
            int v = g_bsum[type * 64 + c];
            g_bsum[type * 64 + c] = run;
            run += v;
        }
    }
}

__global__ __launch_bounds__(1024) void scan3_kernel() {
    int type = blockIdx.y, chunk = blockIdx.x;
    int idx = chunk * 1024 + threadIdx.x;
    if (idx < NN) {
        int o = g_off[type * NN + idx] + g_bsum[type * 64 + chunk];
        g_off[type * NN + idx] = o;
        g_cur[type * NN + idx] = o;
    }
}

// ---------------------------------------------------------------
// boundary MLP: b[t][n] = sigmoid(MLP(x[t][n]))   128->64->32->1
// ---------------------------------------------------------------
__global__ __launch_bounds__(128) void boundary_kernel(
    const float* __restrict__ x,
    const float* __restrict__ bdW1, const float* __restrict__ bdb1,
    const float* __restrict__ bdW2, const float* __restrict__ bdb2,
    const float* __restrict__ bdW3, const float* __restrict__ bdb3)
{
    __shared__ float W1s[128 * 64];
    __shared__ float W2s[64 * 32];
    __shared__ float W3s[32];
    __shared__ float b1s[64], b2s[32];
    __shared__ float b3s;

    int type = blockIdx.y;
    int tid = threadIdx.x;
    const float* W1 = bdW1 + (size_t)type * 128 * 64;
    const float* W2 = bdW2 + (size_t)type * 64 * 32;
    for (int i = tid; i < 128 * 64; i += 128) W1s[i] = W1[i];
    for (int i = tid; i < 64 * 32; i += 128) W2s[i] = W2[i];
    if (tid < 32) W3s[tid] = bdW3[type * 32 + tid];
    if (tid < 64) b1s[tid] = bdb1[type * 64 + tid];
    if (tid < 32) b2s[tid] = bdb2[type * 32 + tid];
    if (tid == 0) b3s = bdb3[type];
    __syncthreads();

    int node = blockIdx.x * 128 + tid;
    if (node >= NN) return;

    const float4* xr = (const float4*)(x + ((size_t)type * NN + node) * DD);

    float h1[64];
#pragma unroll
    for (int j = 0; j < 64; j++) h1[j] = b1s[j];

    for (int d4 = 0; d4 < 32; d4++) {
        float4 xv = xr[d4];
        float vs[4] = {xv.x, xv.y, xv.z, xv.w};
#pragma unroll
        for (int dd = 0; dd < 4; dd++) {
            float v = vs[dd];
            const float4* wr = (const float4*)&W1s[(d4 * 4 + dd) * 64];
#pragma unroll
            for (int q = 0; q < 16; q++) {
                float4 w = wr[q];
                h1[q * 4 + 0] += v * w.x;
                h1[q * 4 + 1] += v * w.y;
                h1[q * 4 + 2] += v * w.z;
                h1[q * 4 + 3] += v * w.w;
            }
        }
    }
#pragma unroll
    for (int j = 0; j < 64; j++) h1[j] = fmaxf(h1[j], 0.f);

    float h2[32];
#pragma unroll
    for (int j = 0; j < 32; j++) h2[j] = b2s[j];
#pragma unroll
    for (int k = 0; k < 64; k++) {
        float v = h1[k];
        const float4* wr = (const float4*)&W2s[k * 32];
#pragma unroll
        for (int q = 0; q < 8; q++) {
            float4 w = wr[q];
            h2[q * 4 + 0] += v * w.x;
            h2[q * 4 + 1] += v * w.y;
            h2[q * 4 + 2] += v * w.z;
            h2[q * 4 + 3] += v * w.w;
        }
    }
    float z = b3s;
#pragma unroll
    for (int k = 0; k < 32; k++) z += fmaxf(h2[k], 0.f) * W3s[k];

    g_b[type * NN + node] = 1.f / (1.f + expf(-z));
}

// ---------------------------------------------------------------
// helpers
// ---------------------------------------------------------------
__device__ __forceinline__ void load_rows_to_h16(
    __half* dst, const float* src, int row0, int rowlim, int nrows, int tid)
{
    for (int idx = tid; idx < nrows * 32; idx += 256) {
        int r = idx >> 5, c4 = idx & 31;
        int row = row0 + r;
        float4 v = (row < rowlim) ? ((const float4*)(src + (size_t)row * DD))[c4]
                                  : make_float4(0.f, 0.f, 0.f, 0.f);
        __half2* d = (__half2*)&dst[r * APITCH + c4 * 4];
        d[0] = __floats2half2_rn(v.x, v.y);
        d[1] = __floats2half2_rn(v.z, v.w);
    }
}

__device__ __forceinline__ void load_w_to_h16(
    __half* dst, const float* w, int tid)
{
    for (int idx = tid; idx < 128 * 32; idx += 256) {
        int r = idx >> 5, c4 = idx & 31;
        float4 v = ((const float4*)(w + (size_t)r * DD))[c4];
        __half2* d = (__half2*)&dst[r * APITCH + c4 * 4];
        d[0] = __floats2half2_rn(v.x, v.y);
        d[1] = __floats2half2_rn(v.z, v.w);
    }
}

// wmma gemm: C(64x128) = A(64x128) @ B(128x128)
// 8 warps: wm = wid&3 (16 rows each), wn = wid>>2 (64 cols each)
__device__ __forceinline__ void wmma_tile64(
    const __half* Ah, const __half* Bh, float* Cs, int wid)
{
    int wm = wid & 3, wn = wid >> 2;
    wmma::fragment<wmma::accumulator, 16, 16, 16, float> acc[4];
#pragma unroll
    for (int j = 0; j < 4; j++) wmma::fill_fragment(acc[j], 0.f);

#pragma unroll
    for (int k = 0; k < 8; k++) {
        wmma::fragment<wmma::matrix_a, 16, 16, 16, __half, wmma::row_major> a;
        wmma::fragment<wmma::matrix_b, 16, 16, 16, __half, wmma::row_major> b[4];
        wmma::load_matrix_sync(a, Ah + (wm * 16) * APITCH + k * 16, APITCH);
#pragma unroll
        for (int j = 0; j < 4; j++)
            wmma::load_matrix_sync(b[j], Bh + (k * 16) * APITCH + wn * 64 + j * 16, APITCH);
#pragma unroll
        for (int j = 0; j < 4; j++)
            wmma::mma_sync(acc[j], a, b[j], acc[j]);
    }
#pragma unroll
    for (int j = 0; j < 4; j++)
        wmma::store_matrix_sync(Cs + (wm * 16) * CPITCH + wn * 64 + j * 16,
                                acc[j], CPITCH, wmma::mem_row_major);
}

// ---------------------------------------------------------------
// et (tensor core): t = relu(x @ W1 + b1) @ W2 + b2  -> g_t (fp16)
// 64-row tiles, 2 CTAs/SM
// ---------------------------------------------------------------
__global__ __launch_bounds__(256, 2) void et_wmma_kernel(
    const float* __restrict__ x,
    const float* __restrict__ W1g, const float* __restrict__ b1g,
    const float* __restrict__ W2g, const float* __restrict__ b2g)
{
    extern __shared__ char smem_raw[];
    __half* Ah = (__half*)smem_raw;                  // 64*APITCH halves
    __half* Bh = Ah + 64 * APITCH;                   // 128*APITCH halves
    float*  Cs = (float*)(Bh + 128 * APITCH);        // 64*CPITCH floats

    int type = blockIdx.y;
    int m0 = blockIdx.x * GTM;
    int tid = threadIdx.x;
    int wid = tid >> 5;

    load_rows_to_h16(Ah, x + (size_t)type * NN * DD, m0, NN, 64, tid);
    load_w_to_h16(Bh, W1g + (size_t)type * 128 * 128, tid);
    __syncthreads();

    wmma_tile64(Ah, Bh, Cs, wid);
    __syncthreads();

    // bias + relu -> Ah (fp16), reload W2
    const float* b1 = b1g + type * 128;
    for (int idx = tid; idx < 64 * 64; idx += 256) {
        int r = idx >> 6, c2 = (idx & 63) * 2;
        float z0 = Cs[r * CPITCH + c2]     + b1[c2];
        float z1 = Cs[r * CPITCH + c2 + 1] + b1[c2 + 1];
        *(__half2*)&Ah[r * APITCH + c2] = __floats2half2_rn(fmaxf(z0, 0.f), fmaxf(z1, 0.f));
    }
    load_w_to_h16(Bh, W2g + (size_t)type * 128 * 128, tid);
    __syncthreads();

    wmma_tile64(Ah, Bh, Cs, wid);
    __syncthreads();

    const float* b2 = b2g + type * 128;
    __half2* tb = (__half2*)(g_t + (size_t)type * NN * DD);
    for (int idx = tid; idx < 64 * 64; idx += 256) {
        int r = idx >> 6, c2idx = idx & 63;
        int row = m0 + r;
        if (row < NN) {
            int c2 = c2idx * 2;
            float z0 = Cs[r * CPITCH + c2]     + b2[c2];
            float z1 = Cs[r * CPITCH + c2 + 1] + b2[c2 + 1];
            tb[(size_t)row * 64 + c2idx] = __floats2half2_rn(z0, z1);
        }
    }
}

// ---------------------------------------------------------------
// per-edge coefficient MLP + CSR binning (fused)
// ---------------------------------------------------------------
__global__ __launch_bounds__(256) void coef_order_kernel(
    const int* __restrict__ ei, const float* __restrict__ ea,
    const float* __restrict__ bwW1, const float* __restrict__ bwb1,
    const float* __restrict__ bwW2, const float* __restrict__ bwb2,
    const float* __restrict__ bwW3, const float* __restrict__ bwb3)
{
    __shared__ float W1s[64], B1s[32], W2s[512], B2s[16], W3s[16];
    __shared__ float B3s;
    int type = blockIdx.y;
    int tid = threadIdx.x;
    if (tid < 64) W1s[tid] = bwW1[type * 64 + tid];
    if (tid < 32) B1s[tid] = bwb1[type * 32 + tid];
    for (int i = tid; i < 512; i += 256) W2s[i] = bwW2[type * 512 + i];
    if (tid < 16) B2s[tid] = bwb2[type * 16 + tid];
    if (tid < 16) W3s[tid] = bwW3[type * 16 + tid];
    if (tid == 0) B3s = bwb3[type];
    __syncthreads();

    int j = blockIdx.x * 256 + tid;
    if (j >= EE) return;
    const int* eib = ei + (size_t)type * 2 * EE;
    int s = eib[j];
    int d = eib[EE + j];
    float sb = g_b[type * NN + s];
    float db = g_b[(1 - type) * NN + d];

    float h1[32];
#pragma unroll
    for (int q = 0; q < 32; q++)
        h1[q] = fmaxf(sb * W1s[q] + db * W1s[32 + q] + B1s[q], 0.f);

    float4 h2v[4];
#pragma unroll
    for (int p = 0; p < 4; p++) h2v[p] = ((const float4*)B2s)[p];
    const float4* W2v = (const float4*)W2s;
#pragma unroll
    for (int q = 0; q < 32; q++) {
        float v = h1[q];
#pragma unroll
        for (int p = 0; p < 4; p++) {
            float4 w = W2v[q * 4 + p];
            h2v[p].x += v * w.x;
            h2v[p].y += v * w.y;
            h2v[p].z += v * w.z;
            h2v[p].w += v * w.w;
        }
    }
    float z = B3s;
#pragma unroll
    for (int p = 0; p < 4; p++) {
        z += fmaxf(h2v[p].x, 0.f) * W3s[p * 4 + 0];
        z += fmaxf(h2v[p].y, 0.f) * W3s[p * 4 + 1];
        z += fmaxf(h2v[p].z, 0.f) * W3s[p * 4 + 2];
        z += fmaxf(h2v[p].w, 0.f) * W3s[p * 4 + 3];
    }

    float w = 1.f / (1.f + expf(-z));
    if (sb > 0.3f || db > 0.3f) w *= 2.f;
    float c = ea[(size_t)type * EE + j] * w;

    int pos = atomicAdd(&g_cur[type * NN + d], 1);
    g_srcA[(size_t)type * EE + pos] = s;
    g_cvalA[(size_t)type * EE + pos] = c;
}

// ---------------------------------------------------------------
// gather: upd[to][n] = x[to][n] + sum over CSR(type e=1-to, dst n)
// ---------------------------------------------------------------
__global__ __launch_bounds__(256) void gather_kernel(const float* __restrict__ x)
{
    int to = blockIdx.y;
    int e = 1 - to;
    int lane = threadIdx.x & 31;
    int warp = threadIdx.x >> 5;
    int n = blockIdx.x * 8 + warp;
    if (n >= NN) return;

    int base = e * NN + n;
    int st = g_off[base];
    int en = g_cur[base];

    const uint2* tb = (const uint2*)(g_t + (size_t)e * NN * DD);
    const int* srcp = g_srcA + (size_t)e * EE;
    const float* cvp = g_cvalA + (size_t)e * EE;

    float4 acc = ((const float4*)(x + ((size_t)to * NN + n) * DD))[lane];

    int i = st;
    for (; i + 3 < en; i += 4) {
        int s0 = __ldg(srcp + i),     s1 = __ldg(srcp + i + 1);
        int s2 = __ldg(srcp + i + 2), s3 = __ldg(srcp + i + 3);
        float c0 = __ldg(cvp + i),     c1 = __ldg(cvp + i + 1);
        float c2 = __ldg(cvp + i + 2), c3 = __ldg(cvp + i + 3);
        uint2 h0 = tb[(size_t)s0 * 32 + lane];
        uint2 h1 = tb[(size_t)s1 * 32 + lane];
        uint2 h2 = tb[(size_t)s2 * 32 + lane];
        uint2 h3 = tb[(size_t)s3 * 32 + lane];
        float2 a0 = __half22float2(*(__half2*)&h0.x), b0 = __half22float2(*(__half2*)&h0.y);
        float2 a1 = __half22float2(*(__half2*)&h1.x), b1 = __half22float2(*(__half2*)&h1.y);
        float2 a2 = __half22float2(*(__half2*)&h2.x), b2 = __half22float2(*(__half2*)&h2.y);
        float2 a3 = __half22float2(*(__half2*)&h3.x), b3 = __half22float2(*(__half2*)&h3.y);
        acc.x += a0.x * c0; acc.y += a0.y * c0; acc.z += b0.x * c0; acc.w += b0.y * c0;
        acc.x += a1.x * c1; acc.y += a1.y * c1; acc.z += b1.x * c1; acc.w += b1.y * c1;
        acc.x += a2.x * c2; acc.y += a2.y * c2; acc.z += b2.x * c2; acc.w += b2.y * c2;
        acc.x += a3.x * c3; acc.y += a3.y * c3; acc.z += b3.x * c3; acc.w += b3.y * c3;
    }
    for (; i < en; i++) {
        int s0 = __ldg(srcp + i);
        float c0 = __ldg(cvp + i);
        uint2 h0 = tb[(size_t)s0 * 32 + lane];
        float2 a0 = __half22float2(*(__half2*)&h0.x), b0 = __half22float2(*(__half2*)&h0.y);
        acc.x += a0.x * c0; acc.y += a0.y * c0; acc.z += b0.x * c0; acc.w += b0.y * c0;
    }

    ((float4*)(g_upd + ((size_t)to * NN + n) * DD))[lane] = acc;
}

// ---------------------------------------------------------------
// nu (tensor core): out = relu(LN(upd @ nuW + nub) * g + b)
// 64-row tiles, 2 CTAs/SM
// ---------------------------------------------------------------
__global__ __launch_bounds__(256, 2) void nu_wmma_kernel(
    const float* __restrict__ nuW, const float* __restrict__ nub,
    const float* __restrict__ lng, const float* __restrict__ lnb,
    float* __restrict__ out)
{
    extern __shared__ char smem_raw[];
    __half* Ah = (__half*)smem_raw;
    __half* Bh = Ah + 64 * APITCH;
    float*  Cs = (float*)(Bh + 128 * APITCH);
    float*  nubS = Cs + 64 * CPITCH;    // 128
    float*  gS   = nubS + 128;          // 128
    float*  lbS  = gS + 128;            // 128

    int type = blockIdx.y;
    int m0 = blockIdx.x * GTM;
    int tid = threadIdx.x;
    int wid = tid >> 5;
    int lane = tid & 31;

    load_rows_to_h16(Ah, g_upd + (size_t)type * NN * DD, m0, NN, 64, tid);
    load_w_to_h16(Bh, nuW + (size_t)type * 128 * 128, tid);
    if (tid < 128) {
        nubS[tid] = nub[type * 128 + tid];
        gS[tid]   = lng[type * 128 + tid];
        lbS[tid]  = lnb[type * 128 + tid];
    }
    __syncthreads();

    wmma_tile64(Ah, Bh, Cs, wid);
    __syncthreads();

    // LN + relu epilogue: warp per 8 rows, lane owns 4 columns
    float* ob = out + (size_t)type * NN * DD;
    float4 bb = ((const float4*)nubS)[lane];
    float4 gg = ((const float4*)gS)[lane];
    float4 ll = ((const float4*)lbS)[lane];

    for (int rr = 0; rr < 8; rr++) {
        int r = wid * 8 + rr;
        int row = m0 + r;
        float4 c = ((const float4*)(Cs + r * CPITCH))[lane];
        c.x += bb.x; c.y += bb.y; c.z += bb.z; c.w += bb.w;
        float s = c.x + c.y + c.z + c.w;
#pragma unroll
        for (int o = 16; o > 0; o >>= 1) s += __shfl_xor_sync(0xffffffffu, s, o);
        float mu = s * (1.f / 128.f);
        float dx = c.x - mu, dy = c.y - mu, dz = c.z - mu, dw = c.w - mu;
        float v = dx * dx + dy * dy + dz * dz + dw * dw;
#pragma unroll
        for (int o = 16; o > 0; o >>= 1) v += __shfl_xor_sync(0xffffffffu, v, o);
        float rs = rsqrtf(v * (1.f / 128.f) + 1e-5f);
        if (row < NN) {
            float4 o4;
            o4.x = fmaxf(dx * rs * gg.x + ll.x, 0.f);
            o4.y = fmaxf(dy * rs * gg.y + ll.y, 0.f);
            o4.z = fmaxf(dz * rs * gg.z + ll.z, 0.f);
            o4.w = fmaxf(dw * rs * gg.w + ll.w, 0.f);
            ((float4*)(ob + (size_t)row * DD))[lane] = o4;
        }
    }
}

// ---------------------------------------------------------------
extern "C" void kernel_launch(void* const* d_in, const int* in_sizes, int n_in,
                              void* d_out, int out_size)
{
    const float* x    = (const float*)d_in[0];
    const int*   ei   = (const int*)d_in[1];
    const float* ea   = (const float*)d_in[2];
    const float* bdW1 = (const float*)d_in[3];
    const float* bdb1 = (const float*)d_in[4];
    const float* bdW2 = (const float*)d_in[5];
    const float* bdb2 = (const float*)d_in[6];
    const float* bdW3 = (const float*)d_in[7];
    const float* bdb3 = (const float*)d_in[8];
    const float* etW1 = (const float*)d_in[9];
    const float* etb1 = (const float*)d_in[10];
    const float* etW2 = (const float*)d_in[11];
    const float* etb2 = (const float*)d_in[12];
    const float* bwW1 = (const float*)d_in[13];
    const float* bwb1 = (const float*)d_in[14];
    const float* bwW2 = (const float*)d_in[15];
    const float* bwb2 = (const float*)d_in[16];
    const float* bwW3 = (const float*)d_in[17];
    const float* bwb3 = (const float*)d_in[18];
    const float* nuW  = (const float*)d_in[19];
    const float* nub  = (const float*)d_in[20];
    const float* lng  = (const float*)d_in[21];
    const float* lnb  = (const float*)d_in[22];
    float* out = (float*)d_out;

    // smem: A 64 rows (h16) + B 128 rows (h16) + C 64 rows (f32)
    const int SMEM_GEMM = (64 + 128) * APITCH * 2 + 64 * CPITCH * 4;   // 86016
    const int SMEM_NU   = SMEM_GEMM + 3 * 128 * 4;                     // +1536
    cudaFuncSetAttribute((const void*)et_wmma_kernel,
                         cudaFuncAttributeMaxDynamicSharedMemorySize, SMEM_GEMM);
    cudaFuncSetAttribute((const void*)nu_wmma_kernel,
                         cudaFuncAttributeMaxDynamicSharedMemorySize, SMEM_NU);

    prep_kernel<<<(2 * NN + 255) / 256, 256>>>();
    hist_kernel<<<dim3((EE + 255) / 256, 2), 256>>>(ei);
    scan1_kernel<<<dim3(NCHUNK, 2), 1024>>>();
    et_wmma_kernel<<<dim3(NTILE, 2), 256, SMEM_GEMM>>>(x, etW1, etb1, etW2, etb2);
    scan2_kernel<<<1, 32>>>();
    scan3_kernel<<<dim3(NCHUNK, 2), 1024>>>();
    boundary_kernel<<<dim3((NN + 127) / 128, 2), 128>>>(x, bdW1, bdb1, bdW2, bdb2, bdW3, bdb3);
    coef_order_kernel<<<dim3((EE + 255) / 256, 2), 256>>>(ei, ea, bwW1, bwb1, bwW2, bwb2, bwW3, bwb3);
    gather_kernel<<<dim3((NN + 7) / 8, 2), 256>>>(x);
    nu_wmma_kernel<<<dim3(NTILE, 2), 256, SMEM_NU>>>(nuW, nub, lng, lnb, out);
}

// round 8
// speedup vs baseline: 2.8140x; 1.1420x over previous
#include <cuda_runtime.h>
#include <cuda_fp16.h>
#include <cuda_bf16.h>
#include <mma.h>
#include <math.h>

using namespace nvcuda;

#define NN 50000
#define DD 128
#define EE 800000
#define NCHUNK 49   // ceil(50000/1024)

#define APITCH 136  // half pitch (272B = 17 uint4) for fp16 smem tiles
#define CPITCH 132  // float pitch for C smem tile
#define GTM 64      // gemm M tile (rows per CTA)
#define NTILE 782   // ceil(50000/64)

// -------- device scratch (no runtime allocation allowed) --------
__device__ float  g_b[2 * NN];                 // boundary scores
__device__ __half g_t[2 * (size_t)NN * DD];    // transformed features (fp16)
__device__ __half g_xh[2 * (size_t)NN * DD];   // x in fp16
__device__ __half g_updh[2 * (size_t)NN * DD]; // x + aggregated messages (fp16)
__device__ __half g_etW1h[2 * 128 * 128];
__device__ __half g_etW2h[2 * 128 * 128];
__device__ __half g_nuWh[2 * 128 * 128];
__device__ int    g_cnt[2 * NN];
__device__ int    g_off[2 * NN];
__device__ int    g_cur[2 * NN];
__device__ int    g_bsum[2 * 64];
__device__ int    g_srcA[2 * (size_t)EE];
__device__ float  g_cvalA[2 * (size_t)EE];

// ---------------------------------------------------------------
__global__ void prep_kernel() {
    int i = blockIdx.x * blockDim.x + threadIdx.x;
    if (i < 2 * NN) g_cnt[i] = 0;
}

// weights f32 -> f16 (once)
__global__ void convw_kernel(const float* __restrict__ etW1,
                             const float* __restrict__ etW2,
                             const float* __restrict__ nuW) {
    int i = blockIdx.x * 256 + threadIdx.x;   // each thread: 4 floats
    const int per = 2 * 128 * 128 / 4;        // 8192
    const float* src; __half* dst; int k;
    if (i < per)            { src = etW1; dst = g_etW1h; k = i; }
    else if (i < 2 * per)   { src = etW2; dst = g_etW2h; k = i - per; }
    else if (i < 3 * per)   { src = nuW;  dst = g_nuWh;  k = i - 2 * per; }
    else return;
    float4 v = ((const float4*)src)[k];
    __half2* d = (__half2*)dst + (size_t)k * 2;
    d[0] = __floats2half2_rn(v.x, v.y);
    d[1] = __floats2half2_rn(v.z, v.w);
}

// x f32 -> f16 (once)
__global__ __launch_bounds__(256) void convx_kernel(const float* __restrict__ x) {
    size_t i = (size_t)blockIdx.x * 256 + threadIdx.x;  // 4 floats each
    size_t total = (size_t)2 * NN * DD / 4;
    if (i < total) {
        float4 v = ((const float4*)x)[i];
        __half2* d = (__half2*)g_xh + i * 2;
        d[0] = __floats2half2_rn(v.x, v.y);
        d[1] = __floats2half2_rn(v.z, v.w);
    }
}

__global__ __launch_bounds__(256) void hist_kernel(const int* __restrict__ ei) {
    int type = blockIdx.y;
    int j = blockIdx.x * 256 + threadIdx.x;
    if (j >= EE) return;
    int d = ei[(size_t)type * 2 * EE + EE + j];
    atomicAdd(&g_cnt[type * NN + d], 1);
}

// ---------------------------------------------------------------
// decoupled 3-phase exclusive scan
// ---------------------------------------------------------------
__global__ __launch_bounds__(1024) void scan1_kernel() {
    __shared__ int warpsums[32];
    int type = blockIdx.y, chunk = blockIdx.x;
    int tid = threadIdx.x, lane = tid & 31, wid = tid >> 5;
    int idx = chunk * 1024 + tid;
    int v = (idx < NN) ? g_cnt[type * NN + idx] : 0;
    int inc = v;
#pragma unroll
    for (int o = 1; o < 32; o <<= 1) {
        int y = __shfl_up_sync(0xffffffffu, inc, o);
        if (lane >= o) inc += y;
    }
    if (lane == 31) warpsums[wid] = inc;
    __syncthreads();
    if (tid < 32) {
        int w = warpsums[tid];
        int s = w;
#pragma unroll
        for (int o = 1; o < 32; o <<= 1) {
            int y = __shfl_up_sync(0xffffffffu, s, o);
            if (tid >= o) s += y;
        }
        warpsums[tid] = s - w;
    }
    __syncthreads();
    int excl = inc - v + warpsums[wid];
    if (idx < NN) g_off[type * NN + idx] = excl;
    if (tid == 1023) g_bsum[type * 64 + chunk] = excl + v;
}

__global__ void scan2_kernel() {
    int type = threadIdx.x;
    if (type < 2) {
        int run = 0;
        for (int c = 0; c < NCHUNK; c++) {
            int v = g_bsum[type * 64 + c];
            g_bsum[type * 64 + c] = run;
            run += v;
        }
    }
}

__global__ __launch_bounds__(1024) void scan3_kernel() {
    int type = blockIdx.y, chunk = blockIdx.x;
    int idx = chunk * 1024 + threadIdx.x;
    if (idx < NN) {
        int o = g_off[type * NN + idx] + g_bsum[type * 64 + chunk];
        g_off[type * NN + idx] = o;
        g_cur[type * NN + idx] = o;
    }
}

// ---------------------------------------------------------------
// boundary MLP (fp32, deliberately: feeds discontinuous >0.3 branch)
// ---------------------------------------------------------------
__global__ __launch_bounds__(128) void boundary_kernel(
    const float* __restrict__ x,
    const float* __restrict__ bdW1, const float* __restrict__ bdb1,
    const float* __restrict__ bdW2, const float* __restrict__ bdb2,
    const float* __restrict__ bdW3, const float* __restrict__ bdb3)
{
    __shared__ float W1s[128 * 64];
    __shared__ float W2s[64 * 32];
    __shared__ float W3s[32];
    __shared__ float b1s[64], b2s[32];
    __shared__ float b3s;

    int type = blockIdx.y;
    int tid = threadIdx.x;
    const float* W1 = bdW1 + (size_t)type * 128 * 64;
    const float* W2 = bdW2 + (size_t)type * 64 * 32;
    for (int i = tid; i < 128 * 64; i += 128) W1s[i] = W1[i];
    for (int i = tid; i < 64 * 32; i += 128) W2s[i] = W2[i];
    if (tid < 32) W3s[tid] = bdW3[type * 32 + tid];
    if (tid < 64) b1s[tid] = bdb1[type * 64 + tid];
    if (tid < 32) b2s[tid] = bdb2[type * 32 + tid];
    if (tid == 0) b3s = bdb3[type];
    __syncthreads();

    int node = blockIdx.x * 128 + tid;
    if (node >= NN) return;

    const float4* xr = (const float4*)(x + ((size_t)type * NN + node) * DD);

    float h1[64];
#pragma unroll
    for (int j = 0; j < 64; j++) h1[j] = b1s[j];

    for (int d4 = 0; d4 < 32; d4++) {
        float4 xv = xr[d4];
        float vs[4] = {xv.x, xv.y, xv.z, xv.w};
#pragma unroll
        for (int dd = 0; dd < 4; dd++) {
            float v = vs[dd];
            const float4* wr = (const float4*)&W1s[(d4 * 4 + dd) * 64];
#pragma unroll
            for (int q = 0; q < 16; q++) {
                float4 w = wr[q];
                h1[q * 4 + 0] += v * w.x;
                h1[q * 4 + 1] += v * w.y;
                h1[q * 4 + 2] += v * w.z;
                h1[q * 4 + 3] += v * w.w;
            }
        }
    }
#pragma unroll
    for (int j = 0; j < 64; j++) h1[j] = fmaxf(h1[j], 0.f);

    float h2[32];
#pragma unroll
    for (int j = 0; j < 32; j++) h2[j] = b2s[j];
#pragma unroll
    for (int k = 0; k < 64; k++) {
        float v = h1[k];
        const float4* wr = (const float4*)&W2s[k * 32];
#pragma unroll
        for (int q = 0; q < 8; q++) {
            float4 w = wr[q];
            h2[q * 4 + 0] += v * w.x;
            h2[q * 4 + 1] += v * w.y;
            h2[q * 4 + 2] += v * w.z;
            h2[q * 4 + 3] += v * w.w;
        }
    }
    float z = b3s;
#pragma unroll
    for (int k = 0; k < 32; k++) z += fmaxf(h2[k], 0.f) * W3s[k];

    g_b[type * NN + node] = 1.f / (1.f + expf(-z));
}

// ---------------------------------------------------------------
// wmma gemm: C(64x128) = A(64x128) @ B(128x128), immediate store
// 8 warps: wm = wid&3 (16 rows each), wn = wid>>2 (64 cols each)
// ---------------------------------------------------------------
__device__ __forceinline__ void wmma_tile64(
    const __half* Ah, const __half* Bh, float* Cs, int wid)
{
    int wm = wid & 3, wn = wid >> 2;
    wmma::fragment<wmma::accumulator, 16, 16, 16, float> acc[4];
#pragma unroll
    for (int j = 0; j < 4; j++) wmma::fill_fragment(acc[j], 0.f);

#pragma unroll
    for (int k = 0; k < 8; k++) {
        wmma::fragment<wmma::matrix_a, 16, 16, 16, __half, wmma::row_major> a;
        wmma::fragment<wmma::matrix_b, 16, 16, 16, __half, wmma::row_major> b[4];
        wmma::load_matrix_sync(a, Ah + (wm * 16) * APITCH + k * 16, APITCH);
#pragma unroll
        for (int j = 0; j < 4; j++)
            wmma::load_matrix_sync(b[j], Bh + (k * 16) * APITCH + wn * 64 + j * 16, APITCH);
#pragma unroll
        for (int j = 0; j < 4; j++)
            wmma::mma_sync(acc[j], a, b[j], acc[j]);
    }
#pragma unroll
    for (int j = 0; j < 4; j++)
        wmma::store_matrix_sync(Cs + (wm * 16) * CPITCH + wn * 64 + j * 16,
                                acc[j], CPITCH, wmma::mem_row_major);
}

// fp16 tile loaders: pure uint4 copies (no conversion)
__device__ __forceinline__ void copy_rows_h16(
    __half* dst, const __half* src, int row0, int rowlim, int tid)
{
    uint4* d = (uint4*)dst;
    const uint4* s = (const uint4*)src;
    for (int i = tid; i < 64 * 16; i += 256) {
        int r = i >> 4, c = i & 15;
        int row = row0 + r;
        uint4 v = make_uint4(0u, 0u, 0u, 0u);
        if (row < rowlim) v = s[(size_t)row * 16 + c];
        d[r * 17 + c] = v;                    // APITCH = 136 halves = 17 uint4
    }
}

__device__ __forceinline__ void copy_w_h16(
    __half* dst, const __half* src, int tid)
{
    uint4* d = (uint4*)dst;
    const uint4* s = (const uint4*)src;
    for (int i = tid; i < 128 * 16; i += 256) {
        int r = i >> 4, c = i & 15;
        d[r * 17 + c] = s[r * 16 + c];
    }
}

// ---------------------------------------------------------------
// et (tensor core): t = relu(x @ W1 + b1) @ W2 + b2  -> g_t (fp16)
// both weight tiles resident; Cs aliases B1h (dead after mma1)
// ---------------------------------------------------------------
__global__ __launch_bounds__(256, 2) void et_wmma_kernel(
    const float* __restrict__ b1g, const float* __restrict__ b2g)
{
    extern __shared__ char smem_raw[];
    __half* Ah  = (__half*)smem_raw;           // 64*APITCH
    __half* B1h = Ah + 64 * APITCH;            // 128*APITCH
    __half* B2h = B1h + 128 * APITCH;          // 128*APITCH
    float*  Cs  = (float*)B1h;                 // alias (33792B <= 34816B)

    int type = blockIdx.y;
    int m0 = blockIdx.x * GTM;
    int tid = threadIdx.x;
    int wid = tid >> 5;
    int wm = wid & 3, wn = wid >> 2;

    copy_rows_h16(Ah, g_xh + (size_t)type * NN * DD, m0, NN, tid);
    copy_w_h16(B1h, g_etW1h + type * 128 * 128, tid);
    copy_w_h16(B2h, g_etW2h + type * 128 * 128, tid);
    __syncthreads();

    // mma1: compute into register fragments, delay store until all B1 reads done
    wmma::fragment<wmma::accumulator, 16, 16, 16, float> acc[4];
#pragma unroll
    for (int j = 0; j < 4; j++) wmma::fill_fragment(acc[j], 0.f);
#pragma unroll
    for (int k = 0; k < 8; k++) {
        wmma::fragment<wmma::matrix_a, 16, 16, 16, __half, wmma::row_major> a;
        wmma::fragment<wmma::matrix_b, 16, 16, 16, __half, wmma::row_major> b[4];
        wmma::load_matrix_sync(a, Ah + (wm * 16) * APITCH + k * 16, APITCH);
#pragma unroll
        for (int j = 0; j < 4; j++)
            wmma::load_matrix_sync(b[j], B1h + (k * 16) * APITCH + wn * 64 + j * 16, APITCH);
#pragma unroll
        for (int j = 0; j < 4; j++)
            wmma::mma_sync(acc[j], a, b[j], acc[j]);
    }
    __syncthreads();   // all warps done reading B1h
#pragma unroll
    for (int j = 0; j < 4; j++)
        wmma::store_matrix_sync(Cs + (wm * 16) * CPITCH + wn * 64 + j * 16,
                                acc[j], CPITCH, wmma::mem_row_major);
    __syncthreads();

    // bias + relu -> Ah (fp16)
    const float* b1 = b1g + type * 128;
    for (int idx = tid; idx < 64 * 64; idx += 256) {
        int r = idx >> 6, c2 = (idx & 63) * 2;
        float z0 = Cs[r * CPITCH + c2]     + b1[c2];
        float z1 = Cs[r * CPITCH + c2 + 1] + b1[c2 + 1];
        *(__half2*)&Ah[r * APITCH + c2] = __floats2half2_rn(fmaxf(z0, 0.f), fmaxf(z1, 0.f));
    }
    __syncthreads();

    // mma2: B2h reads, store to Cs (aliases B1h only — safe)
    wmma_tile64(Ah, B2h, Cs, wid);
    __syncthreads();

    const float* b2 = b2g + type * 128;
    __half2* tb = (__half2*)(g_t + (size_t)type * NN * DD);
    for (int idx = tid; idx < 64 * 64; idx += 256) {
        int r = idx >> 6, c2idx = idx & 63;
        int row = m0 + r;
        if (row < NN) {
            int c2 = c2idx * 2;
            float z0 = Cs[r * CPITCH + c2]     + b2[c2];
            float z1 = Cs[r * CPITCH + c2 + 1] + b2[c2 + 1];
            tb[(size_t)row * 64 + c2idx] = __floats2half2_rn(z0, z1);
        }
    }
}

// ---------------------------------------------------------------
// per-edge coefficient MLP + CSR binning (fused, fp32)
// ---------------------------------------------------------------
__global__ __launch_bounds__(256) void coef_order_kernel(
    const int* __restrict__ ei, const float* __restrict__ ea,
    const float* __restrict__ bwW1, const float* __restrict__ bwb1,
    const float* __restrict__ bwW2, const float* __restrict__ bwb2,
    const float* __restrict__ bwW3, const float* __restrict__ bwb3)
{
    __shared__ float W1s[64], B1s[32], W2s[512], B2s[16], W3s[16];
    __shared__ float B3s;
    int type = blockIdx.y;
    int tid = threadIdx.x;
    if (tid < 64) W1s[tid] = bwW1[type * 64 + tid];
    if (tid < 32) B1s[tid] = bwb1[type * 32 + tid];
    for (int i = tid; i < 512; i += 256) W2s[i] = bwW2[type * 512 + i];
    if (tid < 16) B2s[tid] = bwb2[type * 16 + tid];
    if (tid < 16) W3s[tid] = bwW3[type * 16 + tid];
    if (tid == 0) B3s = bwb3[type];
    __syncthreads();

    int j = blockIdx.x * 256 + tid;
    if (j >= EE) return;
    const int* eib = ei + (size_t)type * 2 * EE;
    int s = eib[j];
    int d = eib[EE + j];
    float sb = g_b[type * NN + s];
    float db = g_b[(1 - type) * NN + d];

    float h1[32];
#pragma unroll
    for (int q = 0; q < 32; q++)
        h1[q] = fmaxf(sb * W1s[q] + db * W1s[32 + q] + B1s[q], 0.f);

    float4 h2v[4];
#pragma unroll
    for (int p = 0; p < 4; p++) h2v[p] = ((const float4*)B2s)[p];
    const float4* W2v = (const float4*)W2s;
#pragma unroll
    for (int q = 0; q < 32; q++) {
        float v = h1[q];
#pragma unroll
        for (int p = 0; p < 4; p++) {
            float4 w = W2v[q * 4 + p];
            h2v[p].x += v * w.x;
            h2v[p].y += v * w.y;
            h2v[p].z += v * w.z;
            h2v[p].w += v * w.w;
        }
    }
    float z = B3s;
#pragma unroll
    for (int p = 0; p < 4; p++) {
        z += fmaxf(h2v[p].x, 0.f) * W3s[p * 4 + 0];
        z += fmaxf(h2v[p].y, 0.f) * W3s[p * 4 + 1];
        z += fmaxf(h2v[p].z, 0.f) * W3s[p * 4 + 2];
        z += fmaxf(h2v[p].w, 0.f) * W3s[p * 4 + 3];
    }

    float w = 1.f / (1.f + expf(-z));
    if (sb > 0.3f || db > 0.3f) w *= 2.f;
    float c = ea[(size_t)type * EE + j] * w;

    int pos = atomicAdd(&g_cur[type * NN + d], 1);
    g_srcA[(size_t)type * EE + pos] = s;
    g_cvalA[(size_t)type * EE + pos] = c;
}

// ---------------------------------------------------------------
// gather: updh[to][n] = fp16(x[to][n] + sum over CSR(e=1-to, dst n))
// ---------------------------------------------------------------
__global__ __launch_bounds__(256) void gather_kernel(const float* __restrict__ x)
{
    int to = blockIdx.y;
    int e = 1 - to;
    int lane = threadIdx.x & 31;
    int warp = threadIdx.x >> 5;
    int n = blockIdx.x * 8 + warp;
    if (n >= NN) return;

    int base = e * NN + n;
    int st = g_off[base];
    int en = g_cur[base];

    const uint2* tb = (const uint2*)(g_t + (size_t)e * NN * DD);
    const int* srcp = g_srcA + (size_t)e * EE;
    const float* cvp = g_cvalA + (size_t)e * EE;

    float4 acc = ((const float4*)(x + ((size_t)to * NN + n) * DD))[lane];

    int i = st;
    for (; i + 3 < en; i += 4) {
        int s0 = __ldg(srcp + i),     s1 = __ldg(srcp + i + 1);
        int s2 = __ldg(srcp + i + 2), s3 = __ldg(srcp + i + 3);
        float c0 = __ldg(cvp + i),     c1 = __ldg(cvp + i + 1);
        float c2 = __ldg(cvp + i + 2), c3 = __ldg(cvp + i + 3);
        uint2 h0 = tb[(size_t)s0 * 32 + lane];
        uint2 h1 = tb[(size_t)s1 * 32 + lane];
        uint2 h2 = tb[(size_t)s2 * 32 + lane];
        uint2 h3 = tb[(size_t)s3 * 32 + lane];
        float2 a0 = __half22float2(*(__half2*)&h0.x), b0 = __half22float2(*(__half2*)&h0.y);
        float2 a1 = __half22float2(*(__half2*)&h1.x), b1 = __half22float2(*(__half2*)&h1.y);
        float2 a2 = __half22float2(*(__half2*)&h2.x), b2 = __half22float2(*(__half2*)&h2.y);
        float2 a3 = __half22float2(*(__half2*)&h3.x), b3 = __half22float2(*(__half2*)&h3.y);
        acc.x += a0.x * c0; acc.y += a0.y * c0; acc.z += b0.x * c0; acc.w += b0.y * c0;
        acc.x += a1.x * c1; acc.y += a1.y * c1; acc.z += b1.x * c1; acc.w += b1.y * c1;
        acc.x += a2.x * c2; acc.y += a2.y * c2; acc.z += b2.x * c2; acc.w += b2.y * c2;
        acc.x += a3.x * c3; acc.y += a3.y * c3; acc.z += b3.x * c3; acc.w += b3.y * c3;
    }
    for (; i < en; i++) {
        int s0 = __ldg(srcp + i);
        float c0 = __ldg(cvp + i);
        uint2 h0 = tb[(size_t)s0 * 32 + lane];
        float2 a0 = __half22float2(*(__half2*)&h0.x), b0 = __half22float2(*(__half2*)&h0.y);
        acc.x += a0.x * c0; acc.y += a0.y * c0; acc.z += b0.x * c0; acc.w += b0.y * c0;
    }

    __half2 p0 = __floats2half2_rn(acc.x, acc.y);
    __half2 p1 = __floats2half2_rn(acc.z, acc.w);
    uint2 u;
    u.x = *(unsigned*)&p0;
    u.y = *(unsigned*)&p1;
    ((uint2*)(g_updh + ((size_t)to * NN + n) * DD))[lane] = u;
}

// ---------------------------------------------------------------
// nu (tensor core): out = relu(LN(updh @ nuW + nub) * g + b)
// ---------------------------------------------------------------
__global__ __launch_bounds__(256, 2) void nu_wmma_kernel(
    const float* __restrict__ nub,
    const float* __restrict__ lng, const float* __restrict__ lnb,
    float* __restrict__ out)
{
    extern __shared__ char smem_raw[];
    __half* Ah = (__half*)smem_raw;
    __half* Bh = Ah + 64 * APITCH;
    float*  Cs = (float*)(Bh + 128 * APITCH);
    float*  nubS = Cs + 64 * CPITCH;    // 128
    float*  gS   = nubS + 128;          // 128
    float*  lbS  = gS + 128;            // 128

    int type = blockIdx.y;
    int m0 = blockIdx.x * GTM;
    int tid = threadIdx.x;
    int wid = tid >> 5;
    int lane = tid & 31;

    copy_rows_h16(Ah, g_updh + (size_t)type * NN * DD, m0, NN, tid);
    copy_w_h16(Bh, g_nuWh + type * 128 * 128, tid);
    if (tid < 128) {
        nubS[tid] = nub[type * 128 + tid];
        gS[tid]   = lng[type * 128 + tid];
        lbS[tid]  = lnb[type * 128 + tid];
    }
    __syncthreads();

    wmma_tile64(Ah, Bh, Cs, wid);
    __syncthreads();

    // LN + relu epilogue: warp per 8 rows, lane owns 4 columns
    float* ob = out + (size_t)type * NN * DD;
    float4 bb = ((const float4*)nubS)[lane];
    float4 gg = ((const float4*)gS)[lane];
    float4 ll = ((const float4*)lbS)[lane];

    for (int rr = 0; rr < 8; rr++) {
        int r = wid * 8 + rr;
        int row = m0 + r;
        float4 c = ((const float4*)(Cs + r * CPITCH))[lane];
        c.x += bb.x; c.y += bb.y; c.z += bb.z; c.w += bb.w;
        float s = c.x + c.y + c.z + c.w;
#pragma unroll
        for (int o = 16; o > 0; o >>= 1) s += __shfl_xor_sync(0xffffffffu, s, o);
        float mu = s * (1.f / 128.f);
        float dx = c.x - mu, dy = c.y - mu, dz = c.z - mu, dw = c.w - mu;
        float v = dx * dx + dy * dy + dz * dz + dw * dw;
#pragma unroll
        for (int o = 16; o > 0; o >>= 1) v += __shfl_xor_sync(0xffffffffu, v, o);
        float rs = rsqrtf(v * (1.f / 128.f) + 1e-5f);
        if (row < NN) {
            float4 o4;
            o4.x = fmaxf(dx * rs * gg.x + ll.x, 0.f);
            o4.y = fmaxf(dy * rs * gg.y + ll.y, 0.f);
            o4.z = fmaxf(dz * rs * gg.z + ll.z, 0.f);
            o4.w = fmaxf(dw * rs * gg.w + ll.w, 0.f);
            ((float4*)(ob + (size_t)row * DD))[lane] = o4;
        }
    }
}

// ---------------------------------------------------------------
extern "C" void kernel_launch(void* const* d_in, const int* in_sizes, int n_in,
                              void* d_out, int out_size)
{
    const float* x    = (const float*)d_in[0];
    const int*   ei   = (const int*)d_in[1];
    const float* ea   = (const float*)d_in[2];
    const float* bdW1 = (const float*)d_in[3];
    const float* bdb1 = (const float*)d_in[4];
    const float* bdW2 = (const float*)d_in[5];
    const float* bdb2 = (const float*)d_in[6];
    const float* bdW3 = (const float*)d_in[7];
    const float* bdb3 = (const float*)d_in[8];
    const float* etW1 = (const float*)d_in[9];
    const float* etb1 = (const float*)d_in[10];
    const float* etW2 = (const float*)d_in[11];
    const float* etb2 = (const float*)d_in[12];
    const float* bwW1 = (const float*)d_in[13];
    const float* bwb1 = (const float*)d_in[14];
    const float* bwW2 = (const float*)d_in[15];
    const float* bwb2 = (const float*)d_in[16];
    const float* bwW3 = (const float*)d_in[17];
    const float* bwb3 = (const float*)d_in[18];
    const float* nuW  = (const float*)d_in[19];
    const float* nub  = (const float*)d_in[20];
    const float* lng  = (const float*)d_in[21];
    const float* lnb  = (const float*)d_in[22];
    float* out = (float*)d_out;

    // et: A + W1 + W2 (fp16), C aliases W1 region
    const int SMEM_ET = (64 + 128 + 128) * APITCH * 2;              // 87040
    // nu: A + W (fp16) + C (f32) + 3*128 f32
    const int SMEM_NU = (64 + 128) * APITCH * 2 + 64 * CPITCH * 4 + 3 * 128 * 4; // 87552
    cudaFuncSetAttribute((const void*)et_wmma_kernel,
                         cudaFuncAttributeMaxDynamicSharedMemorySize, SMEM_ET);
    cudaFuncSetAttribute((const void*)nu_wmma_kernel,
                         cudaFuncAttributeMaxDynamicSharedMemorySize, SMEM_NU);

    prep_kernel<<<(2 * NN + 255) / 256, 256>>>();
    convw_kernel<<<96, 256>>>(etW1, etW2, nuW);
    convx_kernel<<<(2 * NN * DD / 4 + 255) / 256, 256>>>(x);
    et_wmma_kernel<<<dim3(NTILE, 2), 256, SMEM_ET>>>(etb1, etb2);
    hist_kernel<<<dim3((EE + 255) / 256, 2), 256>>>(ei);
    scan1_kernel<<<dim3(NCHUNK, 2), 1024>>>();
    scan2_kernel<<<1, 32>>>();
    scan3_kernel<<<dim3(NCHUNK, 2), 1024>>>();
    boundary_kernel<<<dim3((NN + 127) / 128, 2), 128>>>(x, bdW1, bdb1, bdW2, bdb2, bdW3, bdb3);
    coef_order_kernel<<<dim3((EE + 255) / 256, 2), 256>>>(ei, ea, bwW1, bwb1, bwW2, bwb2, bwW3, bwb3);
    gather_kernel<<<dim3((NN + 7) / 8, 2), 256>>>(x);
    nu_wmma_kernel<<<dim3(NTILE, 2), 256, SMEM_NU>>>(nub, lng, lnb, out);
}